// round 2
// baseline (speedup 1.0000x reference)
#include <cuda_runtime.h>
#include <math.h>

// Problem constants
#define LSEQ 131072
#define NB 4            // batch (== heads)
#define NC 64           // channels
#define TT 126          // valid columns per tile
#define THALO 128       // TT + 2 halo
#define NTILES ((LSEQ + TT - 1) / TT)   // 1041
#define K1BLKS 148
#define PART_STRIDE 4224                // 64*64 S + 64 qq + 64 kk

// Scratch (no cudaMalloc allowed)
__device__ float g_part[NB * K1BLKS * PART_STRIDE];
__device__ float g_P[NB * NC * NC];

// ---------------------------------------------------------------------------
// Register-tiled 64xK GEMM helper.
// A: smem, layout A[k*68 + o]  (transposed weights, float4 along o)
// B: smem, layout B[k*132 + l] (row-major columns, float4 along l)
// C: smem, layout C[(o)*ldc + l], computes 4 o x 8 l per thread, 256 threads
// covers 64 x 128 outputs.
// ---------------------------------------------------------------------------
__device__ __forceinline__ void gemm64_smem(const float* __restrict__ A,
                                            const float* __restrict__ B,
                                            float* __restrict__ C,
                                            int ldc, int o0, int lB)
{
    float acc[4][8];
#pragma unroll
    for (int i = 0; i < 4; i++)
#pragma unroll
        for (int j = 0; j < 8; j++) acc[i][j] = 0.f;

#pragma unroll 8
    for (int k = 0; k < 64; k++) {
        float4 a  = *(const float4*)(A + k * 68 + o0);
        float4 b0 = *(const float4*)(B + k * 132 + lB);
        float4 b1 = *(const float4*)(B + k * 132 + lB + 4);
        float av[4] = {a.x, a.y, a.z, a.w};
        float bv[8] = {b0.x, b0.y, b0.z, b0.w, b1.x, b1.y, b1.z, b1.w};
#pragma unroll
        for (int i = 0; i < 4; i++)
#pragma unroll
            for (int j = 0; j < 8; j++) acc[i][j] = fmaf(av[i], bv[j], acc[i][j]);
    }
#pragma unroll
    for (int i = 0; i < 4; i++)
#pragma unroll
        for (int j = 0; j < 8; j++) C[(o0 + i) * ldc + lB + j] = acc[i][j];
}

// ---------------------------------------------------------------------------
// K1: per (b, block) accumulate partial Gram S = sum_l q k^T, and sum q^2,
// sum k^2 per channel. q = dwconv3(Wq @ x), k = dwconv3(Wk @ x).
// ---------------------------------------------------------------------------
__global__ __launch_bounds__(256, 1)
void k1_qk_gram(const float* __restrict__ x,
                const float* __restrict__ w_kv,
                const float* __restrict__ w_kv_dw,
                const float* __restrict__ w_q,
                const float* __restrict__ w_q_dw)
{
    extern __shared__ float sm[];
    float* xs  = sm;            // 64*132 = 8448
    float* ys  = xs + 8448;     // 64*133 = 8512
    float* qs  = ys + 8512;     // 128*64 = 8192  layout [l][c]
    float* ks  = qs + 8192;     // 8192
    float* wsq = ks + 8192;     // 64*68 = 4352   layout [k][o]
    float* wsk = wsq + 4352;    // 4352
    float* wdq = wsk + 4352;    // 192
    float* wdk = wdq + 192;     // 192

    const int tid = threadIdx.x;
    const int b = blockIdx.y;

    // Load + transpose the 1x1 weights
    for (int idx = tid; idx < 4096; idx += 256) {
        int o = idx >> 6, k = idx & 63;
        wsq[k * 68 + o] = w_q[idx];       // Wq[o][k]
        wsk[k * 68 + o] = w_kv[idx];      // Wk = rows 0..63 of w_kv
    }
    for (int idx = tid; idx < 192; idx += 256) {
        wdq[idx] = w_q_dw[idx];
        wdk[idx] = w_kv_dw[idx];          // rows 0..63
    }
    __syncthreads();

    float accS[16];
#pragma unroll
    for (int i = 0; i < 16; i++) accS[i] = 0.f;
    float accqq = 0.f, acckk = 0.f;

    const int cg = tid & 15, dg = tid >> 4;
    const int c0 = cg * 4, d0 = dg * 4;
    const int o0 = (tid >> 4) * 4, lB = (tid & 15) * 8;

    for (int t = blockIdx.x; t < NTILES; t += K1BLKS) {
        const long l0 = (long)t * TT - 1;

        // Load x tile (zero-padded halo)
        for (int idx = tid; idx < NC * THALO; idx += 256) {
            int c = idx >> 7, li = idx & 127;
            long gl = l0 + li;
            float v = 0.f;
            if (gl >= 0 && gl < LSEQ)
                v = x[(long)(b * NC + c) * LSEQ + gl];
            xs[c * 132 + li] = v;
        }
        __syncthreads();

        // y = Wq @ x  (64 x 128 cols)
        gemm64_smem(wsq, xs, ys, 133, o0, lB);
        __syncthreads();

        // q = dwconv3(y) -> qs[l][c], l in [0, TT)
        for (int idx = tid; idx < TT * NC; idx += 256) {
            int c = idx & 63, l = idx >> 6;
            const float* yr = ys + c * 133 + l;
            qs[l * 64 + c] = wdq[c * 3] * yr[0] + wdq[c * 3 + 1] * yr[1]
                           + wdq[c * 3 + 2] * yr[2];
        }
        __syncthreads();

        // y = Wk @ x
        gemm64_smem(wsk, xs, ys, 133, o0, lB);
        __syncthreads();

        // k = dwconv3(y) -> ks[l][c]
        for (int idx = tid; idx < TT * NC; idx += 256) {
            int c = idx & 63, l = idx >> 6;
            const float* yr = ys + c * 133 + l;
            ks[l * 64 + c] = wdk[c * 3] * yr[0] + wdk[c * 3 + 1] * yr[1]
                           + wdk[c * 3 + 2] * yr[2];
        }
        __syncthreads();

        // per-channel squared sums (warps 0-3)
        if (tid < 64) {
            float s = 0.f;
            for (int l = 0; l < TT; l++) { float v = qs[l * 64 + tid]; s = fmaf(v, v, s); }
            accqq += s;
        } else if (tid < 128) {
            int c = tid - 64;
            float s = 0.f;
            for (int l = 0; l < TT; l++) { float v = ks[l * 64 + c]; s = fmaf(v, v, s); }
            acckk += s;
        }

        // Gram: S[c0..c0+3][d0..d0+3] += q k^T
#pragma unroll 2
        for (int l = 0; l < TT; l++) {
            float4 qv = *(const float4*)(qs + l * 64 + c0);
            float4 kv = *(const float4*)(ks + l * 64 + d0);
            float qa[4] = {qv.x, qv.y, qv.z, qv.w};
            float ka[4] = {kv.x, kv.y, kv.z, kv.w};
#pragma unroll
            for (int i = 0; i < 4; i++)
#pragma unroll
                for (int j = 0; j < 4; j++)
                    accS[i * 4 + j] = fmaf(qa[i], ka[j], accS[i * 4 + j]);
        }
        __syncthreads();
    }

    // Write partials (fixed order -> deterministic)
    float* pb = g_part + ((long)b * K1BLKS + blockIdx.x) * PART_STRIDE;
#pragma unroll
    for (int i = 0; i < 4; i++)
#pragma unroll
        for (int j = 0; j < 4; j++)
            pb[(c0 + i) * 64 + d0 + j] = accS[i * 4 + j];
    if (tid < 64) pb[4096 + tid] = accqq;
    else if (tid < 128) pb[4160 + (tid - 64)] = acckk;
}

// ---------------------------------------------------------------------------
// K2: reduce partials, l2-normalize, temperature, softmax over d,
// then P = W_proj @ attn. One block per batch.
// ---------------------------------------------------------------------------
__global__ __launch_bounds__(256)
void k2_softmax(const float* __restrict__ w_proj,
                const float* __restrict__ temperature)
{
    __shared__ float S[4096];
    __shared__ float nq[64];
    __shared__ float nk[64];
    __shared__ float attn[4096];

    const int b = blockIdx.x;
    const int tid = threadIdx.x;

    for (int idx = tid; idx < PART_STRIDE; idx += 256) {
        const float* p = g_part + (long)b * K1BLKS * PART_STRIDE + idx;
        float s = 0.f;
        for (int blk = 0; blk < K1BLKS; blk++) s += p[(long)blk * PART_STRIDE];
        if (idx < 4096) S[idx] = s;
        else if (idx < 4160) nq[idx - 4096] = fmaxf(sqrtf(s), 1e-12f);
        else nk[idx - 4160] = fmaxf(sqrtf(s), 1e-12f);
    }
    __syncthreads();

    const float tempv = temperature[b];
    for (int idx = tid; idx < 4096; idx += 256) {
        int c = idx >> 6, d = idx & 63;
        attn[idx] = tempv * S[idx] / (nq[c] * nk[d]);
    }
    __syncthreads();

    if (tid < 64) {
        const int c = tid;
        float m = -1e30f;
        for (int d = 0; d < 64; d++) m = fmaxf(m, attn[c * 64 + d]);
        float s = 0.f;
        for (int d = 0; d < 64; d++) {
            float e = expf(attn[c * 64 + d] - m);
            attn[c * 64 + d] = e;
            s += e;
        }
        float inv = 1.f / s;
        for (int d = 0; d < 64; d++) attn[c * 64 + d] *= inv;
    }
    __syncthreads();

    // P = W_proj @ attn
    for (int idx = tid; idx < 4096; idx += 256) {
        int o = idx >> 6, d = idx & 63;
        float s = 0.f;
        for (int c = 0; c < 64; c++)
            s = fmaf(w_proj[o * 64 + c], attn[c * 64 + d], s);
        g_P[b * 4096 + idx] = s;
    }
}

// ---------------------------------------------------------------------------
// K3: out = P @ dwconv3(Wv @ x), streamed per tile.
// ---------------------------------------------------------------------------
__global__ __launch_bounds__(256, 2)
void k3_out(const float* __restrict__ x,
            const float* __restrict__ w_kv,
            const float* __restrict__ w_kv_dw,
            float* __restrict__ out)
{
    extern __shared__ float sm[];
    float* xs  = sm;            // 8448 (vs aliases this after yv is done)
    float* yv  = xs + 8448;     // 64*132 = 8448
    float* wsv = yv + 8448;     // 4352  [k][o]
    float* ps  = wsv + 4352;    // 4352  [c][o]  (P transposed)
    float* wdv = ps + 4352;     // 192
    float* vs  = xs;            // alias

    const int tid = threadIdx.x;
    const int b = blockIdx.y;
    const int t = blockIdx.x;

    for (int idx = tid; idx < 4096; idx += 256) {
        int o = idx >> 6, k = idx & 63;
        wsv[k * 68 + o] = w_kv[(64 + o) * 64 + k];   // Wv = rows 64..127
        ps[k * 68 + o]  = g_P[b * 4096 + idx];       // ps[c][o] = P[o][c]
    }
    for (int idx = tid; idx < 192; idx += 256)
        wdv[idx] = w_kv_dw[192 + idx];               // rows 64..127
    // no sync needed yet: xs load below doesn't touch these
    const long l0 = (long)t * TT - 1;
    for (int idx = tid; idx < NC * THALO; idx += 256) {
        int c = idx >> 7, li = idx & 127;
        long gl = l0 + li;
        float v = 0.f;
        if (gl >= 0 && gl < LSEQ)
            v = x[(long)(b * NC + c) * LSEQ + gl];
        xs[c * 132 + li] = v;
    }
    __syncthreads();

    const int o0 = (tid >> 4) * 4, lB = (tid & 15) * 8;

    // yv = Wv @ x
    gemm64_smem(wsv, xs, yv, 132, o0, lB);
    __syncthreads();

    // v = dwconv3(yv) -> vs[c][l] (aliases xs; yv read, xs dead)
    for (int idx = tid; idx < NC * THALO; idx += 256) {
        int c = idx >> 7, l = idx & 127;
        if (l < TT) {
            const float* yr = yv + c * 132 + l;
            vs[c * 132 + l] = wdv[c * 3] * yr[0] + wdv[c * 3 + 1] * yr[1]
                            + wdv[c * 3 + 2] * yr[2];
        }
    }
    __syncthreads();

    // out tile = P @ v   (contract over c)
    {
        float acc[4][8];
#pragma unroll
        for (int i = 0; i < 4; i++)
#pragma unroll
            for (int j = 0; j < 8; j++) acc[i][j] = 0.f;

#pragma unroll 8
        for (int c = 0; c < 64; c++) {
            float4 a  = *(const float4*)(ps + c * 68 + o0);
            float4 b0 = *(const float4*)(vs + c * 132 + lB);
            float4 b1 = *(const float4*)(vs + c * 132 + lB + 4);
            float av[4] = {a.x, a.y, a.z, a.w};
            float bv[8] = {b0.x, b0.y, b0.z, b0.w, b1.x, b1.y, b1.z, b1.w};
#pragma unroll
            for (int i = 0; i < 4; i++)
#pragma unroll
                for (int j = 0; j < 8; j++) acc[i][j] = fmaf(av[i], bv[j], acc[i][j]);
        }

#pragma unroll
        for (int i = 0; i < 4; i++) {
#pragma unroll
            for (int j = 0; j < 8; j++) {
                int l = lB + j;
                long gl = (long)t * TT + l;
                if (l < TT && gl < LSEQ)
                    out[(long)(b * NC + o0 + i) * LSEQ + gl] = acc[i][j];
            }
        }
    }
}

// ---------------------------------------------------------------------------
extern "C" void kernel_launch(void* const* d_in, const int* in_sizes, int n_in,
                              void* d_out, int out_size)
{
    const float* x           = (const float*)d_in[0];
    const float* w_kv        = (const float*)d_in[1];
    const float* w_kv_dw     = (const float*)d_in[2];
    const float* w_q         = (const float*)d_in[3];
    const float* w_q_dw      = (const float*)d_in[4];
    const float* w_proj      = (const float*)d_in[5];
    const float* temperature = (const float*)d_in[6];
    float* out = (float*)d_out;

    const int SM1 = 42432 * 4;   // 169728 B
    const int SM3 = 25792 * 4;   // 103168 B
    cudaFuncSetAttribute(k1_qk_gram, cudaFuncAttributeMaxDynamicSharedMemorySize, SM1);
    cudaFuncSetAttribute(k3_out,     cudaFuncAttributeMaxDynamicSharedMemorySize, SM3);

    k1_qk_gram<<<dim3(K1BLKS, NB), 256, SM1>>>(x, w_kv, w_kv_dw, w_q, w_q_dw);
    k2_softmax<<<NB, 256>>>(w_proj, temperature);
    k3_out<<<dim3(NTILES, NB), 256, SM3>>>(x, w_kv, w_kv_dw, out);
}

// round 3
// speedup vs baseline: 1.0105x; 1.0105x over previous
#include <cuda_runtime.h>
#include <math.h>

// Problem constants
#define LSEQ 131072
#define NB 4            // batch (== heads)
#define NC 64           // channels
#define TT 126          // valid columns per tile
#define THALO 128       // TT + 2 halo
#define NTILES ((LSEQ + TT - 1) / TT)   // 1041
#define K1BLKS 148
#define PART_STRIDE 4224                // 64*64 S + 64 qq + 64 kk

// Scratch (no cudaMalloc allowed)
__device__ float g_part[NB * K1BLKS * PART_STRIDE];
__device__ float g_P[NB * NC * NC];

// ---------------------------------------------------------------------------
// Register-tiled 64xK GEMM helper.
// A: smem, layout A[k*68 + o]  (transposed weights, float4 along o)
// B: smem, layout B[k*132 + l] (row-major columns, float4 along l)
// C: smem, layout C[(o)*ldc + l], computes 4 o x 8 l per thread, 256 threads
// covers 64 x 128 outputs.
// ---------------------------------------------------------------------------
__device__ __forceinline__ void gemm64_smem(const float* __restrict__ A,
                                            const float* __restrict__ B,
                                            float* __restrict__ C,
                                            int ldc, int o0, int lB)
{
    float acc[4][8];
#pragma unroll
    for (int i = 0; i < 4; i++)
#pragma unroll
        for (int j = 0; j < 8; j++) acc[i][j] = 0.f;

#pragma unroll 8
    for (int k = 0; k < 64; k++) {
        float4 a  = *(const float4*)(A + k * 68 + o0);
        float4 b0 = *(const float4*)(B + k * 132 + lB);
        float4 b1 = *(const float4*)(B + k * 132 + lB + 4);
        float av[4] = {a.x, a.y, a.z, a.w};
        float bv[8] = {b0.x, b0.y, b0.z, b0.w, b1.x, b1.y, b1.z, b1.w};
#pragma unroll
        for (int i = 0; i < 4; i++)
#pragma unroll
            for (int j = 0; j < 8; j++) acc[i][j] = fmaf(av[i], bv[j], acc[i][j]);
    }
#pragma unroll
    for (int i = 0; i < 4; i++)
#pragma unroll
        for (int j = 0; j < 8; j++) C[(o0 + i) * ldc + lB + j] = acc[i][j];
}

// ---------------------------------------------------------------------------
// K1: per (b, block) accumulate partial Gram S = sum_l q k^T, and sum q^2,
// sum k^2 per channel. q = dwconv3(Wq @ x), k = dwconv3(Wk @ x).
// ---------------------------------------------------------------------------
__global__ __launch_bounds__(256, 1)
void k1_qk_gram(const float* __restrict__ x,
                const float* __restrict__ w_kv,
                const float* __restrict__ w_kv_dw,
                const float* __restrict__ w_q,
                const float* __restrict__ w_q_dw)
{
    extern __shared__ float sm[];
    float* xs  = sm;            // 64*132 = 8448
    float* ys  = xs + 8448;     // 64*133 = 8512
    float* qs  = ys + 8512;     // 128*64 = 8192  layout [l][c]
    float* ks  = qs + 8192;     // 8192
    float* wsq = ks + 8192;     // 64*68 = 4352   layout [k][o]
    float* wsk = wsq + 4352;    // 4352
    float* wdq = wsk + 4352;    // 192
    float* wdk = wdq + 192;     // 192

    const int tid = threadIdx.x;
    const int b = blockIdx.y;

    // Load + transpose the 1x1 weights
    for (int idx = tid; idx < 4096; idx += 256) {
        int o = idx >> 6, k = idx & 63;
        wsq[k * 68 + o] = w_q[idx];       // Wq[o][k]
        wsk[k * 68 + o] = w_kv[idx];      // Wk = rows 0..63 of w_kv
    }
    for (int idx = tid; idx < 192; idx += 256) {
        wdq[idx] = w_q_dw[idx];
        wdk[idx] = w_kv_dw[idx];          // rows 0..63
    }
    __syncthreads();

    float accS[16];
#pragma unroll
    for (int i = 0; i < 16; i++) accS[i] = 0.f;
    float accqq = 0.f, acckk = 0.f;

    const int cg = tid & 15, dg = tid >> 4;
    const int c0 = cg * 4, d0 = dg * 4;
    const int o0 = (tid >> 4) * 4, lB = (tid & 15) * 8;

    for (int t = blockIdx.x; t < NTILES; t += K1BLKS) {
        const long l0 = (long)t * TT - 1;

        // Load x tile (zero-padded halo)
        for (int idx = tid; idx < NC * THALO; idx += 256) {
            int c = idx >> 7, li = idx & 127;
            long gl = l0 + li;
            float v = 0.f;
            if (gl >= 0 && gl < LSEQ)
                v = x[(long)(b * NC + c) * LSEQ + gl];
            xs[c * 132 + li] = v;
        }
        __syncthreads();

        // y = Wq @ x  (64 x 128 cols)
        gemm64_smem(wsq, xs, ys, 133, o0, lB);
        __syncthreads();

        // q = dwconv3(y) -> qs[l][c], l in [0, TT)
        for (int idx = tid; idx < TT * NC; idx += 256) {
            int c = idx & 63, l = idx >> 6;
            const float* yr = ys + c * 133 + l;
            qs[l * 64 + c] = wdq[c * 3] * yr[0] + wdq[c * 3 + 1] * yr[1]
                           + wdq[c * 3 + 2] * yr[2];
        }
        __syncthreads();

        // y = Wk @ x
        gemm64_smem(wsk, xs, ys, 133, o0, lB);
        __syncthreads();

        // k = dwconv3(y) -> ks[l][c]
        for (int idx = tid; idx < TT * NC; idx += 256) {
            int c = idx & 63, l = idx >> 6;
            const float* yr = ys + c * 133 + l;
            ks[l * 64 + c] = wdk[c * 3] * yr[0] + wdk[c * 3 + 1] * yr[1]
                           + wdk[c * 3 + 2] * yr[2];
        }
        __syncthreads();

        // per-channel squared sums (warps 0-3)
        if (tid < 64) {
            float s = 0.f;
            for (int l = 0; l < TT; l++) { float v = qs[l * 64 + tid]; s = fmaf(v, v, s); }
            accqq += s;
        } else if (tid < 128) {
            int c = tid - 64;
            float s = 0.f;
            for (int l = 0; l < TT; l++) { float v = ks[l * 64 + c]; s = fmaf(v, v, s); }
            acckk += s;
        }

        // Gram: S[c0..c0+3][d0..d0+3] += q k^T
#pragma unroll 2
        for (int l = 0; l < TT; l++) {
            float4 qv = *(const float4*)(qs + l * 64 + c0);
            float4 kv = *(const float4*)(ks + l * 64 + d0);
            float qa[4] = {qv.x, qv.y, qv.z, qv.w};
            float ka[4] = {kv.x, kv.y, kv.z, kv.w};
#pragma unroll
            for (int i = 0; i < 4; i++)
#pragma unroll
                for (int j = 0; j < 4; j++)
                    accS[i * 4 + j] = fmaf(qa[i], ka[j], accS[i * 4 + j]);
        }
        __syncthreads();
    }

    // Write partials (fixed order -> deterministic)
    float* pb = g_part + ((long)b * K1BLKS + blockIdx.x) * PART_STRIDE;
#pragma unroll
    for (int i = 0; i < 4; i++)
#pragma unroll
        for (int j = 0; j < 4; j++)
            pb[(c0 + i) * 64 + d0 + j] = accS[i * 4 + j];
    if (tid < 64) pb[4096 + tid] = accqq;
    else if (tid < 128) pb[4160 + (tid - 64)] = acckk;
}

// ---------------------------------------------------------------------------
// K2: reduce partials, l2-normalize, temperature, softmax over d,
// then P = W_proj @ attn. One block per batch.
// ---------------------------------------------------------------------------
__global__ __launch_bounds__(256)
void k2_softmax(const float* __restrict__ w_proj,
                const float* __restrict__ temperature)
{
    __shared__ float S[4096];
    __shared__ float nq[64];
    __shared__ float nk[64];
    __shared__ float attn[4096];

    const int b = blockIdx.x;
    const int tid = threadIdx.x;

    for (int idx = tid; idx < PART_STRIDE; idx += 256) {
        const float* p = g_part + (long)b * K1BLKS * PART_STRIDE + idx;
        float s = 0.f;
        for (int blk = 0; blk < K1BLKS; blk++) s += p[(long)blk * PART_STRIDE];
        if (idx < 4096) S[idx] = s;
        else if (idx < 4160) nq[idx - 4096] = fmaxf(sqrtf(s), 1e-12f);
        else nk[idx - 4160] = fmaxf(sqrtf(s), 1e-12f);
    }
    __syncthreads();

    const float tempv = temperature[b];
    for (int idx = tid; idx < 4096; idx += 256) {
        int c = idx >> 6, d = idx & 63;
        attn[idx] = tempv * S[idx] / (nq[c] * nk[d]);
    }
    __syncthreads();

    if (tid < 64) {
        const int c = tid;
        float m = -1e30f;
        for (int d = 0; d < 64; d++) m = fmaxf(m, attn[c * 64 + d]);
        float s = 0.f;
        for (int d = 0; d < 64; d++) {
            float e = expf(attn[c * 64 + d] - m);
            attn[c * 64 + d] = e;
            s += e;
        }
        float inv = 1.f / s;
        for (int d = 0; d < 64; d++) attn[c * 64 + d] *= inv;
    }
    __syncthreads();

    // P = W_proj @ attn
    for (int idx = tid; idx < 4096; idx += 256) {
        int o = idx >> 6, d = idx & 63;
        float s = 0.f;
        for (int c = 0; c < 64; c++)
            s = fmaf(w_proj[o * 64 + c], attn[c * 64 + d], s);
        g_P[b * 4096 + idx] = s;
    }
}

// ---------------------------------------------------------------------------
// K3: out = P @ dwconv3(Wv @ x), streamed per tile.
// ---------------------------------------------------------------------------
__global__ __launch_bounds__(256, 2)
void k3_out(const float* __restrict__ x,
            const float* __restrict__ w_kv,
            const float* __restrict__ w_kv_dw,
            float* __restrict__ out)
{
    extern __shared__ float sm[];
    float* xs  = sm;            // 8448 (vs aliases this after yv is done)
    float* yv  = xs + 8448;     // 64*132 = 8448
    float* wsv = yv + 8448;     // 4352  [k][o]
    float* ps  = wsv + 4352;    // 4352  [c][o]  (P transposed)
    float* wdv = ps + 4352;     // 192
    float* vs  = xs;            // alias

    const int tid = threadIdx.x;
    const int b = blockIdx.y;
    const int t = blockIdx.x;

    for (int idx = tid; idx < 4096; idx += 256) {
        int o = idx >> 6, k = idx & 63;
        wsv[k * 68 + o] = w_kv[(64 + o) * 64 + k];   // Wv = rows 64..127
        ps[k * 68 + o]  = g_P[b * 4096 + idx];       // ps[c][o] = P[o][c]
    }
    for (int idx = tid; idx < 192; idx += 256)
        wdv[idx] = w_kv_dw[192 + idx];               // rows 64..127
    // no sync needed yet: xs load below doesn't touch these
    const long l0 = (long)t * TT - 1;
    for (int idx = tid; idx < NC * THALO; idx += 256) {
        int c = idx >> 7, li = idx & 127;
        long gl = l0 + li;
        float v = 0.f;
        if (gl >= 0 && gl < LSEQ)
            v = x[(long)(b * NC + c) * LSEQ + gl];
        xs[c * 132 + li] = v;
    }
    __syncthreads();

    const int o0 = (tid >> 4) * 4, lB = (tid & 15) * 8;

    // yv = Wv @ x
    gemm64_smem(wsv, xs, yv, 132, o0, lB);
    __syncthreads();

    // v = dwconv3(yv) -> vs[c][l] (aliases xs; yv read, xs dead)
    for (int idx = tid; idx < NC * THALO; idx += 256) {
        int c = idx >> 7, l = idx & 127;
        if (l < TT) {
            const float* yr = yv + c * 132 + l;
            vs[c * 132 + l] = wdv[c * 3] * yr[0] + wdv[c * 3 + 1] * yr[1]
                            + wdv[c * 3 + 2] * yr[2];
        }
    }
    __syncthreads();

    // out tile = P @ v   (contract over c)
    {
        float acc[4][8];
#pragma unroll
        for (int i = 0; i < 4; i++)
#pragma unroll
            for (int j = 0; j < 8; j++) acc[i][j] = 0.f;

#pragma unroll 8
        for (int c = 0; c < 64; c++) {
            float4 a  = *(const float4*)(ps + c * 68 + o0);
            float4 b0 = *(const float4*)(vs + c * 132 + lB);
            float4 b1 = *(const float4*)(vs + c * 132 + lB + 4);
            float av[4] = {a.x, a.y, a.z, a.w};
            float bv[8] = {b0.x, b0.y, b0.z, b0.w, b1.x, b1.y, b1.z, b1.w};
#pragma unroll
            for (int i = 0; i < 4; i++)
#pragma unroll
                for (int j = 0; j < 8; j++) acc[i][j] = fmaf(av[i], bv[j], acc[i][j]);
        }

#pragma unroll
        for (int i = 0; i < 4; i++) {
#pragma unroll
            for (int j = 0; j < 8; j++) {
                int l = lB + j;
                long gl = (long)t * TT + l;
                if (l < TT && gl < LSEQ)
                    out[(long)(b * NC + o0 + i) * LSEQ + gl] = acc[i][j];
            }
        }
    }
}

// ---------------------------------------------------------------------------
extern "C" void kernel_launch(void* const* d_in, const int* in_sizes, int n_in,
                              void* d_out, int out_size)
{
    const float* x           = (const float*)d_in[0];
    const float* w_kv        = (const float*)d_in[1];
    const float* w_kv_dw     = (const float*)d_in[2];
    const float* w_q         = (const float*)d_in[3];
    const float* w_q_dw      = (const float*)d_in[4];
    const float* w_proj      = (const float*)d_in[5];
    const float* temperature = (const float*)d_in[6];
    float* out = (float*)d_out;

    const int SM1 = 42432 * 4;   // 169728 B
    const int SM3 = 25792 * 4;   // 103168 B
    cudaFuncSetAttribute(k1_qk_gram, cudaFuncAttributeMaxDynamicSharedMemorySize, SM1);
    cudaFuncSetAttribute(k3_out,     cudaFuncAttributeMaxDynamicSharedMemorySize, SM3);

    k1_qk_gram<<<dim3(K1BLKS, NB), 256, SM1>>>(x, w_kv, w_kv_dw, w_q, w_q_dw);
    k2_softmax<<<NB, 256>>>(w_proj, temperature);
    k3_out<<<dim3(NTILES, NB), 256, SM3>>>(x, w_kv, w_kv_dw, out);
}

// round 5
// speedup vs baseline: 1.4346x; 1.4197x over previous
#include <cuda_runtime.h>
#include <math.h>

#define LSEQ 131072
#define NB 4
#define T1 256
#define NT1 (LSEQ / T1)     // 512
#define G1X 74
#define TT 126
#define NTILES ((LSEQ + TT - 1) / TT)   // 1041

typedef unsigned long long u64;

// Scratch (no cudaMalloc allowed)
__device__ float g_part[NB * G1X * 3 * 4096];   // partial G0,G1,G2 per block
__device__ float g_Z[NB * 5 * 4096];            // Z0,Z1,Z2,Z1t,Z2t
__device__ float g_gd[NB * 3 * 64];             // diag(Wq G_s Wq^T)
__device__ float g_hd[NB * 3 * 64];             // diag(Wk G_s Wk^T)
__device__ float g_P[NB * 4096];                // Wproj @ attn

// ---------------- packed f32x2 helpers ----------------
__device__ __forceinline__ u64 dup2(float f) {
    u64 r; asm("mov.b64 %0, {%1, %1};" : "=l"(r) : "f"(f)); return r;
}
__device__ __forceinline__ void fma2(u64& d, u64 a, u64 b) {
    asm("fma.rn.f32x2 %0, %1, %2, %0;" : "+l"(d) : "l"(a), "l"(b));
}
__device__ __forceinline__ float2 unpack2(u64 v) {
    float2 r; asm("mov.b64 {%0, %1}, %2;" : "=f"(r.x), "=f"(r.y) : "l"(v)); return r;
}

// ---------------------------------------------------------------------------
// K1: shifted Grams of x: G_s[c][d] = sum_m x_c(m) x_d(m+s), s=0,1,2.
// xs layout [col][c], pitch 68. Each thread: 4 c  x  2 d-pairs  x  3 shifts.
// ---------------------------------------------------------------------------
__global__ __launch_bounds__(256, 2)
void k1_gram(const float* __restrict__ x)
{
    extern __shared__ float xs[];   // 258 * 68 floats
    const int tid = threadIdx.x, lane = tid & 31, warp = tid >> 5;
    const int b = blockIdx.y;
    const int c0 = (tid & 15) * 4, d0 = (tid >> 4) * 4;

    u64 acc[3][4][2];
#pragma unroll
    for (int s = 0; s < 3; s++)
#pragma unroll
        for (int i = 0; i < 4; i++) { acc[s][i][0] = 0ull; acc[s][i][1] = 0ull; }

    for (int t = blockIdx.x; t < NT1; t += G1X) {
        const int m0 = t * T1;
        for (int c = warp; c < 64; c += 8) {
            const float* xp = x + (b * 64 + c) * LSEQ + m0;
            for (int col = lane; col < T1 + 2; col += 32)
                xs[col * 68 + c] = (m0 + col < LSEQ) ? xp[col] : 0.f;
        }
        __syncthreads();

#pragma unroll 2
        for (int l = 0; l < T1; l++) {
            const float* r0 = xs + l * 68;
            float4 av = *(const float4*)(r0 + c0);
            u64 a0 = dup2(av.x), a1 = dup2(av.y), a2 = dup2(av.z), a3 = dup2(av.w);
            ulonglong2 b0 = *(const ulonglong2*)(r0 + d0);
            ulonglong2 b1 = *(const ulonglong2*)(r0 + 68 + d0);
            ulonglong2 b2 = *(const ulonglong2*)(r0 + 136 + d0);
            fma2(acc[0][0][0], a0, b0.x); fma2(acc[0][0][1], a0, b0.y);
            fma2(acc[0][1][0], a1, b0.x); fma2(acc[0][1][1], a1, b0.y);
            fma2(acc[0][2][0], a2, b0.x); fma2(acc[0][2][1], a2, b0.y);
            fma2(acc[0][3][0], a3, b0.x); fma2(acc[0][3][1], a3, b0.y);
            fma2(acc[1][0][0], a0, b1.x); fma2(acc[1][0][1], a0, b1.y);
            fma2(acc[1][1][0], a1, b1.x); fma2(acc[1][1][1], a1, b1.y);
            fma2(acc[1][2][0], a2, b1.x); fma2(acc[1][2][1], a2, b1.y);
            fma2(acc[1][3][0], a3, b1.x); fma2(acc[1][3][1], a3, b1.y);
            fma2(acc[2][0][0], a0, b2.x); fma2(acc[2][0][1], a0, b2.y);
            fma2(acc[2][1][0], a1, b2.x); fma2(acc[2][1][1], a1, b2.y);
            fma2(acc[2][2][0], a2, b2.x); fma2(acc[2][2][1], a2, b2.y);
            fma2(acc[2][3][0], a3, b2.x); fma2(acc[2][3][1], a3, b2.y);
        }
        __syncthreads();
    }

    float* pb = g_part + ((b * G1X + blockIdx.x) * 3) * 4096;
#pragma unroll
    for (int s = 0; s < 3; s++)
#pragma unroll
        for (int i = 0; i < 4; i++)
#pragma unroll
            for (int p = 0; p < 2; p++) {
                float2 v = unpack2(acc[s][i][p]);
                pb[s * 4096 + (c0 + i) * 64 + d0 + 2 * p]     = v.x;
                pb[s * 4096 + (c0 + i) * 64 + d0 + 2 * p + 1] = v.y;
            }
}

// ---------------------------------------------------------------------------
// 64x64x64 matmul: C = A @ B (row-major smem); At=true -> C = A^T @ B
// ---------------------------------------------------------------------------
__device__ __forceinline__ void mm64(const float* __restrict__ A,
                                     const float* __restrict__ B,
                                     float* __restrict__ C, int tid, bool At)
{
    const int i0 = (tid >> 4) * 4, j0 = (tid & 15) * 4;
    float acc[4][4] = {};
    for (int k = 0; k < 64; k++) {
        float a[4];
#pragma unroll
        for (int i = 0; i < 4; i++) a[i] = At ? A[k * 64 + i0 + i] : A[(i0 + i) * 64 + k];
        float4 bv = *(const float4*)(B + k * 64 + j0);
        float bb[4] = {bv.x, bv.y, bv.z, bv.w};
#pragma unroll
        for (int i = 0; i < 4; i++)
#pragma unroll
            for (int j = 0; j < 4; j++) acc[i][j] = fmaf(a[i], bb[j], acc[i][j]);
    }
#pragma unroll
    for (int i = 0; i < 4; i++)
#pragma unroll
        for (int j = 0; j < 4; j++) C[(i0 + i) * 64 + j0 + j] = acc[i][j];
}

// ---------------------------------------------------------------------------
// K2a: block (s,b): reduce G_s; gd_s = diag(Wq G_s Wq^T);
// Z_s = G_s Wk^T (store); hd_s; if s>0 also Zt_s = G_s^T Wk^T.
// ---------------------------------------------------------------------------
__global__ __launch_bounds__(256)
void k2a(const float* __restrict__ w_kv, const float* __restrict__ w_q)
{
    extern __shared__ float sm2[];
    float* sG  = sm2;
    float* sWT = sm2 + 4096;
    float* sM  = sm2 + 8192;
    const int tid = threadIdx.x;
    const int s = blockIdx.x, b = blockIdx.y;

    for (int idx = tid; idx < 4096; idx += 256) {
        const float* p = g_part + ((b * G1X) * 3 + s) * 4096 + idx;
        float acc = 0.f;
        for (int blk = 0; blk < G1X; blk++) acc += p[blk * 3 * 4096];
        sG[idx] = acc;
    }
    for (int idx = tid; idx < 4096; idx += 256)
        sWT[(idx & 63) * 64 + (idx >> 6)] = w_q[idx];
    __syncthreads();

    mm64(sG, sWT, sM, tid, false);          // E = G_s @ Wq^T
    __syncthreads();
    if (tid < 64) {
        float acc = 0.f;
        for (int k = 0; k < 64; k++) acc = fmaf(sWT[k * 64 + tid], sM[k * 64 + tid], acc);
        g_gd[(b * 3 + s) * 64 + tid] = acc;
    }
    __syncthreads();

    for (int idx = tid; idx < 4096; idx += 256)
        sWT[(idx & 63) * 64 + (idx >> 6)] = w_kv[idx];   // Wk rows 0..63
    __syncthreads();

    mm64(sG, sWT, sM, tid, false);          // Z = G_s @ Wk^T
    __syncthreads();
    float* gZ = g_Z + (b * 5 + s) * 4096;
    for (int idx = tid; idx < 4096; idx += 256) gZ[idx] = sM[idx];
    if (tid < 64) {
        float acc = 0.f;
        for (int k = 0; k < 64; k++) acc = fmaf(sWT[k * 64 + tid], sM[k * 64 + tid], acc);
        g_hd[(b * 3 + s) * 64 + tid] = acc;
    }
    __syncthreads();

    if (s > 0) {
        mm64(sG, sWT, sM, tid, true);       // Zt = G_s^T @ Wk^T
        __syncthreads();
        float* gZt = g_Z + (b * 5 + 2 + s) * 4096;   // slots 3 (s=1), 4 (s=2)
        for (int idx = tid; idx < 4096; idx += 256) gZt[idx] = sM[idx];
    }
}

// ---------------------------------------------------------------------------
// K2b: per batch: assemble S (+ edge corrections), norms, softmax,
// P = Wproj @ attn -> g_P.
// ---------------------------------------------------------------------------
__global__ __launch_bounds__(256)
void k2b(const float* __restrict__ x,
         const float* __restrict__ w_kv,
         const float* __restrict__ w_kv_dw,
         const float* __restrict__ w_q,
         const float* __restrict__ w_q_dw,
         const float* __restrict__ w_proj,
         const float* __restrict__ temperature)
{
    extern __shared__ float sm3[];
    float* sZ0  = sm3;
    float* sZ1  = sm3 + 4096;
    float* sZ2  = sm3 + 8192;
    float* sZ1t = sm3 + 12288;
    float* sZ2t = sm3 + 16384;
    float* sW   = sm3 + 20480;
    float* sR   = sm3 + 24576;
    float* sS   = sm3 + 28672;
    float* sP   = sm3 + 32768;

    __shared__ float x0s[64], xLs[64], u0s[64], uLs[64], v0s[64], vLs[64];
    __shared__ float aqs[3][64], bks[3][64], nqs[64], nks[64];

    const int tid = threadIdx.x;
    const int b = blockIdx.x;
    const float tempv = temperature[b];

    for (int idx = tid; idx < 5 * 4096; idx += 256) sm3[idx] = g_Z[b * 5 * 4096 + idx];
    for (int idx = tid; idx < 4096; idx += 256) sW[idx] = w_q[idx];
    if (tid < 64) {
        const int c = tid;
        x0s[c] = x[(b * 64 + c) * LSEQ];
        xLs[c] = x[(b * 64 + c) * LSEQ + LSEQ - 1];
#pragma unroll
        for (int e = 0; e < 3; e++) {
            aqs[e][c] = w_q_dw[c * 3 + e];
            bks[e][c] = w_kv_dw[c * 3 + e];
        }
    }
    __syncthreads();

    if (tid < 64) {
        const int c = tid;
        float a0 = 0.f, aL = 0.f, q0 = 0.f, qL = 0.f;
        for (int k = 0; k < 64; k++) {
            float wk = w_kv[c * 64 + k], wq = w_q[c * 64 + k];
            a0 = fmaf(wk, x0s[k], a0);  aL = fmaf(wk, xLs[k], aL);
            q0 = fmaf(wq, x0s[k], q0);  qL = fmaf(wq, xLs[k], qL);
        }
        u0s[c] = a0; uLs[c] = aL; v0s[c] = q0; vLs[c] = qL;
    }
    __syncthreads();

    // S = sum_{d1} diag(aq_{d1}) (Wq @ R_{d1})
    for (int dd = 0; dd < 3; dd++) {
        for (int idx = tid; idx < 4096; idx += 256) {
            const int i = idx >> 6, j = idx & 63;
            float r;
            if (dd == 0) {          // d1 = -1
                r = (sZ0[idx] - xLs[i] * uLs[j]) * bks[0][j]
                  + sZ1[idx] * bks[1][j] + sZ2[idx] * bks[2][j];
            } else if (dd == 1) {   // d1 = 0
                r = sZ1t[idx] * bks[0][j] + sZ0[idx] * bks[1][j] + sZ1[idx] * bks[2][j];
            } else {                // d1 = +1
                r = sZ2t[idx] * bks[0][j] + sZ1t[idx] * bks[1][j]
                  + (sZ0[idx] - x0s[i] * u0s[j]) * bks[2][j];
            }
            sR[idx] = r;
        }
        __syncthreads();
        {
            const int i0 = (tid >> 4) * 4, j0 = (tid & 15) * 4;
            float acc[4][4] = {};
            for (int k = 0; k < 64; k++) {
                float a[4];
#pragma unroll
                for (int i = 0; i < 4; i++) a[i] = sW[(i0 + i) * 64 + k];
                float4 bv = *(const float4*)(sR + k * 64 + j0);
                float bb[4] = {bv.x, bv.y, bv.z, bv.w};
#pragma unroll
                for (int i = 0; i < 4; i++)
#pragma unroll
                    for (int j = 0; j < 4; j++) acc[i][j] = fmaf(a[i], bb[j], acc[i][j]);
            }
#pragma unroll
            for (int i = 0; i < 4; i++) {
                float scale = aqs[dd][i0 + i];
#pragma unroll
                for (int j = 0; j < 4; j++) {
                    if (dd == 0) sS[(i0 + i) * 64 + j0 + j] = scale * acc[i][j];
                    else         sS[(i0 + i) * 64 + j0 + j] += scale * acc[i][j];
                }
            }
        }
        __syncthreads();
    }

    if (tid < 64) {
        const int c = tid;
        float g0 = g_gd[(b * 3 + 0) * 64 + c], g1 = g_gd[(b * 3 + 1) * 64 + c],
              g2 = g_gd[(b * 3 + 2) * 64 + c];
        float h0 = g_hd[(b * 3 + 0) * 64 + c], h1 = g_hd[(b * 3 + 1) * 64 + c],
              h2 = g_hd[(b * 3 + 2) * 64 + c];
        float am = aqs[0][c], a0 = aqs[1][c], ap = aqs[2][c];
        float bm = bks[0][c], b0 = bks[1][c], bp = bks[2][c];
        float qq = am * am * (g0 - vLs[c] * vLs[c]) + a0 * a0 * g0
                 + ap * ap * (g0 - v0s[c] * v0s[c])
                 + 2.f * (am * a0 + a0 * ap) * g1 + 2.f * am * ap * g2;
        float kk = bm * bm * (h0 - uLs[c] * uLs[c]) + b0 * b0 * h0
                 + bp * bp * (h0 - u0s[c] * u0s[c])
                 + 2.f * (bm * b0 + b0 * bp) * h1 + 2.f * bm * bp * h2;
        nqs[c] = fmaxf(sqrtf(qq), 1e-12f);
        nks[c] = fmaxf(sqrtf(kk), 1e-12f);
    }
    __syncthreads();

    for (int idx = tid; idx < 4096; idx += 256) {
        const int i = idx >> 6, j = idx & 63;
        sS[idx] = tempv * sS[idx] / (nqs[i] * nks[j]);
    }
    __syncthreads();

    if (tid < 64) {
        const int c = tid;
        float m = -1e30f;
        for (int j = 0; j < 64; j++) m = fmaxf(m, sS[c * 64 + j]);
        float sum = 0.f;
        for (int j = 0; j < 64; j++) {
            float e = expf(sS[c * 64 + j] - m);
            sS[c * 64 + j] = e; sum += e;
        }
        float inv = 1.f / sum;
        for (int j = 0; j < 64; j++) sS[c * 64 + j] *= inv;
    }
    __syncthreads();
    for (int idx = tid; idx < 4096; idx += 256) sW[idx] = w_proj[idx];
    __syncthreads();

    mm64(sW, sS, sP, tid, false);           // P = Wproj @ attn
    __syncthreads();
    for (int idx = tid; idx < 4096; idx += 256) g_P[b * 4096 + idx] = sP[idx];
}

// ---------------------------------------------------------------------------
// f32x2 GEMM: C(64 x 128 cols) = A^T-layout weights @ B.
// A [k*68+o], B [k*132+l], C [o*132+l]. Thread: 4 o x 8 l (4 pairs).
// ---------------------------------------------------------------------------
__device__ __forceinline__ void gemm64_f2(const float* __restrict__ A,
                                          const float* __restrict__ B,
                                          float* __restrict__ C,
                                          int o0, int lB)
{
    u64 acc[4][4];
#pragma unroll
    for (int i = 0; i < 4; i++)
#pragma unroll
        for (int p = 0; p < 4; p++) acc[i][p] = 0ull;

#pragma unroll 4
    for (int k = 0; k < 64; k++) {
        float4 av = *(const float4*)(A + k * 68 + o0);
        u64 a[4] = {dup2(av.x), dup2(av.y), dup2(av.z), dup2(av.w)};
        ulonglong2 b01 = *(const ulonglong2*)(B + k * 132 + lB);
        ulonglong2 b23 = *(const ulonglong2*)(B + k * 132 + lB + 4);
        u64 bp[4] = {b01.x, b01.y, b23.x, b23.y};
#pragma unroll
        for (int i = 0; i < 4; i++)
#pragma unroll
            for (int p = 0; p < 4; p++) fma2(acc[i][p], a[i], bp[p]);
    }
#pragma unroll
    for (int i = 0; i < 4; i++)
#pragma unroll
        for (int p = 0; p < 4; p++)
            *(u64*)(C + (o0 + i) * 132 + lB + 2 * p) = acc[i][p];
}

// ---------------------------------------------------------------------------
// K3: out = P @ dwconv3(Wv @ x), streamed per tile (f32x2 GEMMs).
// ---------------------------------------------------------------------------
__global__ __launch_bounds__(256, 2)
void k3_out(const float* __restrict__ x,
            const float* __restrict__ w_kv,
            const float* __restrict__ w_kv_dw,
            float* __restrict__ out)
{
    extern __shared__ float sm4[];
    float* xs  = sm4;            // 64*132 = 8448
    float* yv  = xs + 8448;      // 8448
    float* wsv = yv + 8448;      // 4352  [k][o]
    float* ps  = wsv + 4352;     // 4352  [c][o] (P transposed)
    float* wdv = ps + 4352;      // 192
    float* vs  = xs;             // alias after xs is dead

    const int tid = threadIdx.x;
    const int b = blockIdx.y, t = blockIdx.x;

    for (int idx = tid; idx < 4096; idx += 256) {
        int o = idx >> 6, k = idx & 63;
        wsv[k * 68 + o] = w_kv[(64 + o) * 64 + k];   // Wv rows 64..127
        ps[k * 68 + o]  = g_P[b * 4096 + idx];
    }
    for (int idx = tid; idx < 192; idx += 256)
        wdv[idx] = w_kv_dw[192 + idx];

    const long l0 = (long)t * TT - 1;
    for (int idx = tid; idx < 64 * 128; idx += 256) {
        int c = idx >> 7, li = idx & 127;
        long gl = l0 + li;
        float v = 0.f;
        if (gl >= 0 && gl < LSEQ) v = x[(long)(b * 64 + c) * LSEQ + gl];
        xs[c * 132 + li] = v;
    }
    __syncthreads();

    const int o0 = (tid >> 4) * 4, lB = (tid & 15) * 8;

    gemm64_f2(wsv, xs, yv, o0, lB);     // yv = Wv @ x
    __syncthreads();

    for (int idx = tid; idx < 64 * 128; idx += 256) {
        int c = idx >> 7, l = idx & 127;
        if (l < TT) {
            const float* yr = yv + c * 132 + l;
            vs[c * 132 + l] = wdv[c * 3] * yr[0] + wdv[c * 3 + 1] * yr[1]
                            + wdv[c * 3 + 2] * yr[2];
        }
    }
    __syncthreads();

    {   // out tile = P @ v
        u64 acc[4][4];
#pragma unroll
        for (int i = 0; i < 4; i++)
#pragma unroll
            for (int p = 0; p < 4; p++) acc[i][p] = 0ull;

#pragma unroll 4
        for (int c = 0; c < 64; c++) {
            float4 av = *(const float4*)(ps + c * 68 + o0);
            u64 a[4] = {dup2(av.x), dup2(av.y), dup2(av.z), dup2(av.w)};
            ulonglong2 b01 = *(const ulonglong2*)(vs + c * 132 + lB);
            ulonglong2 b23 = *(const ulonglong2*)(vs + c * 132 + lB + 4);
            u64 bp[4] = {b01.x, b01.y, b23.x, b23.y};
#pragma unroll
            for (int i = 0; i < 4; i++)
#pragma unroll
                for (int p = 0; p < 4; p++) fma2(acc[i][p], a[i], bp[p]);
        }

#pragma unroll
        for (int i = 0; i < 4; i++) {
#pragma unroll
            for (int p = 0; p < 4; p++) {
                float2 v = unpack2(acc[i][p]);
                int l = lB + 2 * p;
                long gl = (long)t * TT + l;
                float* op = out + (long)(b * 64 + o0 + i) * LSEQ;
                if (l < TT && gl < LSEQ) op[gl] = v.x;
                if (l + 1 < TT && gl + 1 < LSEQ) op[gl + 1] = v.y;
            }
        }
    }
}

// ---------------------------------------------------------------------------
extern "C" void kernel_launch(void* const* d_in, const int* in_sizes, int n_in,
                              void* d_out, int out_size)
{
    const float* x           = (const float*)d_in[0];
    const float* w_kv        = (const float*)d_in[1];
    const float* w_kv_dw     = (const float*)d_in[2];
    const float* w_q         = (const float*)d_in[3];
    const float* w_q_dw      = (const float*)d_in[4];
    const float* w_proj      = (const float*)d_in[5];
    const float* temperature = (const float*)d_in[6];
    float* out = (float*)d_out;

    const int SM1  = 258 * 68 * 4;      // 70176
    const int SM2A = 3 * 4096 * 4;      // 49152
    const int SM2B = 9 * 4096 * 4;      // 147456
    const int SM3  = 25792 * 4;         // 103168
    cudaFuncSetAttribute(k1_gram, cudaFuncAttributeMaxDynamicSharedMemorySize, SM1);
    cudaFuncSetAttribute(k2a,     cudaFuncAttributeMaxDynamicSharedMemorySize, SM2A);
    cudaFuncSetAttribute(k2b,     cudaFuncAttributeMaxDynamicSharedMemorySize, SM2B);
    cudaFuncSetAttribute(k3_out,  cudaFuncAttributeMaxDynamicSharedMemorySize, SM3);

    k1_gram<<<dim3(G1X, NB), 256, SM1>>>(x);
    k2a<<<dim3(3, NB), 256, SM2A>>>(w_kv, w_q);
    k2b<<<NB, 256, SM2B>>>(x, w_kv, w_kv_dw, w_q, w_q_dw, w_proj, temperature);
    k3_out<<<dim3(NTILES, NB), 256, SM3>>>(x, w_kv, w_kv_dw, out);
}

// round 7
// speedup vs baseline: 1.8183x; 1.2675x over previous
#include <cuda_runtime.h>
#include <math.h>

#define LSEQ 131072
#define NB 4
#define T1 256
#define NT1 (LSEQ / T1)     // 512
#define G1X 74
#define TT 126
#define NTILES ((LSEQ + TT - 1) / TT)   // 1041
#define G3X 37              // k3 persistent grid.x (37*4 = 148 CTAs)

typedef unsigned long long u64;

// Scratch (no cudaMalloc allowed)
__device__ float g_part[NB * G1X * 3 * 4096];   // partial G0,G1,G2 per block
__device__ float g_Z[NB * 5 * 4096];            // Z0,Z1,Z2,Z1t,Z2t
__device__ float g_gd[NB * 3 * 64];             // diag(Wq G_s Wq^T)
__device__ float g_hd[NB * 3 * 64];             // diag(Wk G_s Wk^T)
__device__ float g_P[NB * 4096];                // Wproj @ attn

// ---------------- packed f32x2 helpers ----------------
__device__ __forceinline__ u64 dup2(float f) {
    u64 r; asm("mov.b64 %0, {%1, %1};" : "=l"(r) : "f"(f)); return r;
}
__device__ __forceinline__ void fma2(u64& d, u64 a, u64 b) {
    asm("fma.rn.f32x2 %0, %1, %2, %0;" : "+l"(d) : "l"(a), "l"(b));
}
__device__ __forceinline__ float2 unpack2(u64 v) {
    float2 r; asm("mov.b64 {%0, %1}, %2;" : "=f"(r.x), "=f"(r.y) : "l"(v)); return r;
}

// ---------------------------------------------------------------------------
// K1: shifted Grams of x: G_s[c][d] = sum_m x_c(m) x_d(m+s), s=0,1,2.
// xs layout [col][c], pitch 68. Each thread: 4 c  x  2 d-pairs  x  3 shifts.
// ---------------------------------------------------------------------------
__global__ __launch_bounds__(256, 2)
void k1_gram(const float* __restrict__ x)
{
    extern __shared__ float xs[];   // 258 * 68 floats
    const int tid = threadIdx.x, lane = tid & 31, warp = tid >> 5;
    const int b = blockIdx.y;
    const int c0 = (tid & 15) * 4, d0 = (tid >> 4) * 4;

    u64 acc[3][4][2];
#pragma unroll
    for (int s = 0; s < 3; s++)
#pragma unroll
        for (int i = 0; i < 4; i++) { acc[s][i][0] = 0ull; acc[s][i][1] = 0ull; }

    for (int t = blockIdx.x; t < NT1; t += G1X) {
        const int m0 = t * T1;
        if (m0 + T1 + 2 <= LSEQ) {
            // fast path: unpredicated vector loads
            for (int c = warp; c < 64; c += 8) {
                const float* xp = x + (long)(b * 64 + c) * LSEQ + m0;
                float* dst = xs + c;
#pragma unroll
                for (int col0 = 0; col0 < T1; col0 += 128) {
                    float4 v = *(const float4*)(xp + col0 + lane * 4);
                    dst[(col0 + lane * 4 + 0) * 68] = v.x;
                    dst[(col0 + lane * 4 + 1) * 68] = v.y;
                    dst[(col0 + lane * 4 + 2) * 68] = v.z;
                    dst[(col0 + lane * 4 + 3) * 68] = v.w;
                }
                if (lane == 0) {
                    dst[T1 * 68]       = xp[T1];
                    dst[(T1 + 1) * 68] = xp[T1 + 1];
                }
            }
        } else {
            for (int c = warp; c < 64; c += 8) {
                const float* xp = x + (long)(b * 64 + c) * LSEQ + m0;
                for (int col = lane; col < T1 + 2; col += 32)
                    xs[col * 68 + c] = (m0 + col < LSEQ) ? xp[col] : 0.f;
            }
        }
        __syncthreads();

#pragma unroll 2
        for (int l = 0; l < T1; l++) {
            const float* r0 = xs + l * 68;
            float4 av = *(const float4*)(r0 + c0);
            u64 a0 = dup2(av.x), a1 = dup2(av.y), a2 = dup2(av.z), a3 = dup2(av.w);
            ulonglong2 b0 = *(const ulonglong2*)(r0 + d0);
            ulonglong2 b1 = *(const ulonglong2*)(r0 + 68 + d0);
            ulonglong2 b2 = *(const ulonglong2*)(r0 + 136 + d0);
            fma2(acc[0][0][0], a0, b0.x); fma2(acc[0][0][1], a0, b0.y);
            fma2(acc[0][1][0], a1, b0.x); fma2(acc[0][1][1], a1, b0.y);
            fma2(acc[0][2][0], a2, b0.x); fma2(acc[0][2][1], a2, b0.y);
            fma2(acc[0][3][0], a3, b0.x); fma2(acc[0][3][1], a3, b0.y);
            fma2(acc[1][0][0], a0, b1.x); fma2(acc[1][0][1], a0, b1.y);
            fma2(acc[1][1][0], a1, b1.x); fma2(acc[1][1][1], a1, b1.y);
            fma2(acc[1][2][0], a2, b1.x); fma2(acc[1][2][1], a2, b1.y);
            fma2(acc[1][3][0], a3, b1.x); fma2(acc[1][3][1], a3, b1.y);
            fma2(acc[2][0][0], a0, b2.x); fma2(acc[2][0][1], a0, b2.y);
            fma2(acc[2][1][0], a1, b2.x); fma2(acc[2][1][1], a1, b2.y);
            fma2(acc[2][2][0], a2, b2.x); fma2(acc[2][2][1], a2, b2.y);
            fma2(acc[2][3][0], a3, b2.x); fma2(acc[2][3][1], a3, b2.y);
        }
        __syncthreads();
    }

    float* pb = g_part + ((b * G1X + blockIdx.x) * 3) * 4096;
#pragma unroll
    for (int s = 0; s < 3; s++)
#pragma unroll
        for (int i = 0; i < 4; i++)
#pragma unroll
            for (int p = 0; p < 2; p++) {
                float2 v = unpack2(acc[s][i][p]);
                pb[s * 4096 + (c0 + i) * 64 + d0 + 2 * p]     = v.x;
                pb[s * 4096 + (c0 + i) * 64 + d0 + 2 * p + 1] = v.y;
            }
}

// ---------------------------------------------------------------------------
// 64x64x64 matmul: C = A @ B (row-major smem); At=true -> C = A^T @ B
// ---------------------------------------------------------------------------
__device__ __forceinline__ void mm64(const float* __restrict__ A,
                                     const float* __restrict__ B,
                                     float* __restrict__ C, int tid, bool At)
{
    const int i0 = (tid >> 4) * 4, j0 = (tid & 15) * 4;
    float acc[4][4] = {};
    for (int k = 0; k < 64; k++) {
        float a[4];
#pragma unroll
        for (int i = 0; i < 4; i++) a[i] = At ? A[k * 64 + i0 + i] : A[(i0 + i) * 64 + k];
        float4 bv = *(const float4*)(B + k * 64 + j0);
        float bb[4] = {bv.x, bv.y, bv.z, bv.w};
#pragma unroll
        for (int i = 0; i < 4; i++)
#pragma unroll
            for (int j = 0; j < 4; j++) acc[i][j] = fmaf(a[i], bb[j], acc[i][j]);
    }
#pragma unroll
    for (int i = 0; i < 4; i++)
#pragma unroll
        for (int j = 0; j < 4; j++) C[(i0 + i) * 64 + j0 + j] = acc[i][j];
}

// ---------------------------------------------------------------------------
// K2a: block (s,b): reduce G_s; gd_s = diag(Wq G_s Wq^T);
// Z_s = G_s Wk^T (store); hd_s; if s>0 also Zt_s = G_s^T Wk^T.
// ---------------------------------------------------------------------------
__global__ __launch_bounds__(256)
void k2a(const float* __restrict__ w_kv, const float* __restrict__ w_q)
{
    extern __shared__ float sm2[];
    float* sG  = sm2;
    float* sWT = sm2 + 4096;
    float* sM  = sm2 + 8192;
    const int tid = threadIdx.x;
    const int s = blockIdx.x, b = blockIdx.y;

    for (int idx = tid; idx < 4096; idx += 256) {
        const float* p = g_part + ((b * G1X) * 3 + s) * 4096 + idx;
        float acc = 0.f;
        for (int blk = 0; blk < G1X; blk++) acc += p[blk * 3 * 4096];
        sG[idx] = acc;
    }
    for (int idx = tid; idx < 4096; idx += 256)
        sWT[(idx & 63) * 64 + (idx >> 6)] = w_q[idx];
    __syncthreads();

    mm64(sG, sWT, sM, tid, false);          // E = G_s @ Wq^T
    __syncthreads();
    if (tid < 64) {
        float acc = 0.f;
        for (int k = 0; k < 64; k++) acc = fmaf(sWT[k * 64 + tid], sM[k * 64 + tid], acc);
        g_gd[(b * 3 + s) * 64 + tid] = acc;
    }
    __syncthreads();

    for (int idx = tid; idx < 4096; idx += 256)
        sWT[(idx & 63) * 64 + (idx >> 6)] = w_kv[idx];   // Wk rows 0..63
    __syncthreads();

    mm64(sG, sWT, sM, tid, false);          // Z = G_s @ Wk^T
    __syncthreads();
    float* gZ = g_Z + (b * 5 + s) * 4096;
    for (int idx = tid; idx < 4096; idx += 256) gZ[idx] = sM[idx];
    if (tid < 64) {
        float acc = 0.f;
        for (int k = 0; k < 64; k++) acc = fmaf(sWT[k * 64 + tid], sM[k * 64 + tid], acc);
        g_hd[(b * 3 + s) * 64 + tid] = acc;
    }
    __syncthreads();

    if (s > 0) {
        mm64(sG, sWT, sM, tid, true);       // Zt = G_s^T @ Wk^T
        __syncthreads();
        float* gZt = g_Z + (b * 5 + 2 + s) * 4096;   // slots 3 (s=1), 4 (s=2)
        for (int idx = tid; idx < 4096; idx += 256) gZt[idx] = sM[idx];
    }
}

// ---------------------------------------------------------------------------
// K2b: per batch: assemble S (+ edge corrections), norms, softmax,
// P = Wproj @ attn -> g_P.
// ---------------------------------------------------------------------------
__global__ __launch_bounds__(256)
void k2b(const float* __restrict__ x,
         const float* __restrict__ w_kv,
         const float* __restrict__ w_kv_dw,
         const float* __restrict__ w_q,
         const float* __restrict__ w_q_dw,
         const float* __restrict__ w_proj,
         const float* __restrict__ temperature)
{
    extern __shared__ float sm3[];
    float* sZ0  = sm3;
    float* sZ1  = sm3 + 4096;
    float* sZ2  = sm3 + 8192;
    float* sZ1t = sm3 + 12288;
    float* sZ2t = sm3 + 16384;
    float* sW   = sm3 + 20480;
    float* sR   = sm3 + 24576;
    float* sS   = sm3 + 28672;
    float* sP   = sm3 + 32768;

    __shared__ float x0s[64], xLs[64], u0s[64], uLs[64], v0s[64], vLs[64];
    __shared__ float aqs[3][64], bks[3][64], nqs[64], nks[64];

    const int tid = threadIdx.x;
    const int b = blockIdx.x;
    const float tempv = temperature[b];

    for (int idx = tid; idx < 5 * 4096; idx += 256) sm3[idx] = g_Z[b * 5 * 4096 + idx];
    for (int idx = tid; idx < 4096; idx += 256) sW[idx] = w_q[idx];
    if (tid < 64) {
        const int c = tid;
        x0s[c] = x[(b * 64 + c) * LSEQ];
        xLs[c] = x[(b * 64 + c) * LSEQ + LSEQ - 1];
#pragma unroll
        for (int e = 0; e < 3; e++) {
            aqs[e][c] = w_q_dw[c * 3 + e];
            bks[e][c] = w_kv_dw[c * 3 + e];
        }
    }
    __syncthreads();

    if (tid < 64) {
        const int c = tid;
        float a0 = 0.f, aL = 0.f, q0 = 0.f, qL = 0.f;
        for (int k = 0; k < 64; k++) {
            float wk = w_kv[c * 64 + k], wq = w_q[c * 64 + k];
            a0 = fmaf(wk, x0s[k], a0);  aL = fmaf(wk, xLs[k], aL);
            q0 = fmaf(wq, x0s[k], q0);  qL = fmaf(wq, xLs[k], qL);
        }
        u0s[c] = a0; uLs[c] = aL; v0s[c] = q0; vLs[c] = qL;
    }
    __syncthreads();

    // S = sum_{d1} diag(aq_{d1}) (Wq @ R_{d1})
    for (int dd = 0; dd < 3; dd++) {
        for (int idx = tid; idx < 4096; idx += 256) {
            const int i = idx >> 6, j = idx & 63;
            float r;
            if (dd == 0) {          // d1 = -1
                r = (sZ0[idx] - xLs[i] * uLs[j]) * bks[0][j]
                  + sZ1[idx] * bks[1][j] + sZ2[idx] * bks[2][j];
            } else if (dd == 1) {   // d1 = 0
                r = sZ1t[idx] * bks[0][j] + sZ0[idx] * bks[1][j] + sZ1[idx] * bks[2][j];
            } else {                // d1 = +1
                r = sZ2t[idx] * bks[0][j] + sZ1t[idx] * bks[1][j]
                  + (sZ0[idx] - x0s[i] * u0s[j]) * bks[2][j];
            }
            sR[idx] = r;
        }
        __syncthreads();
        {
            const int i0 = (tid >> 4) * 4, j0 = (tid & 15) * 4;
            float acc[4][4] = {};
            for (int k = 0; k < 64; k++) {
                float a[4];
#pragma unroll
                for (int i = 0; i < 4; i++) a[i] = sW[(i0 + i) * 64 + k];
                float4 bv = *(const float4*)(sR + k * 64 + j0);
                float bb[4] = {bv.x, bv.y, bv.z, bv.w};
#pragma unroll
                for (int i = 0; i < 4; i++)
#pragma unroll
                    for (int j = 0; j < 4; j++) acc[i][j] = fmaf(a[i], bb[j], acc[i][j]);
            }
#pragma unroll
            for (int i = 0; i < 4; i++) {
                float scale = aqs[dd][i0 + i];
#pragma unroll
                for (int j = 0; j < 4; j++) {
                    if (dd == 0) sS[(i0 + i) * 64 + j0 + j] = scale * acc[i][j];
                    else         sS[(i0 + i) * 64 + j0 + j] += scale * acc[i][j];
                }
            }
        }
        __syncthreads();
    }

    if (tid < 64) {
        const int c = tid;
        float g0 = g_gd[(b * 3 + 0) * 64 + c], g1 = g_gd[(b * 3 + 1) * 64 + c],
              g2 = g_gd[(b * 3 + 2) * 64 + c];
        float h0 = g_hd[(b * 3 + 0) * 64 + c], h1 = g_hd[(b * 3 + 1) * 64 + c],
              h2 = g_hd[(b * 3 + 2) * 64 + c];
        float am = aqs[0][c], a0 = aqs[1][c], ap = aqs[2][c];
        float bm = bks[0][c], b0 = bks[1][c], bp = bks[2][c];
        float qq = am * am * (g0 - vLs[c] * vLs[c]) + a0 * a0 * g0
                 + ap * ap * (g0 - v0s[c] * v0s[c])
                 + 2.f * (am * a0 + a0 * ap) * g1 + 2.f * am * ap * g2;
        float kk = bm * bm * (h0 - uLs[c] * uLs[c]) + b0 * b0 * h0
                 + bp * bp * (h0 - u0s[c] * u0s[c])
                 + 2.f * (bm * b0 + b0 * bp) * h1 + 2.f * bm * bp * h2;
        nqs[c] = fmaxf(sqrtf(qq), 1e-12f);
        nks[c] = fmaxf(sqrtf(kk), 1e-12f);
    }
    __syncthreads();

    for (int idx = tid; idx < 4096; idx += 256) {
        const int i = idx >> 6, j = idx & 63;
        sS[idx] = tempv * sS[idx] / (nqs[i] * nks[j]);
    }
    __syncthreads();

    if (tid < 64) {
        const int c = tid;
        float m = -1e30f;
        for (int j = 0; j < 64; j++) m = fmaxf(m, sS[c * 64 + j]);
        float sum = 0.f;
        for (int j = 0; j < 64; j++) {
            float e = expf(sS[c * 64 + j] - m);
            sS[c * 64 + j] = e; sum += e;
        }
        float inv = 1.f / sum;
        for (int j = 0; j < 64; j++) sS[c * 64 + j] *= inv;
    }
    __syncthreads();
    for (int idx = tid; idx < 4096; idx += 256) sW[idx] = w_proj[idx];
    __syncthreads();

    mm64(sW, sS, sP, tid, false);           // P = Wproj @ attn
    __syncthreads();
    for (int idx = tid; idx < 4096; idx += 256) g_P[b * 4096 + idx] = sP[idx];
}

// ---------------------------------------------------------------------------
// cp.async helpers
// ---------------------------------------------------------------------------
__device__ __forceinline__ void cpa_commit() {
    asm volatile("cp.async.commit_group;" ::: "memory");
}
__device__ __forceinline__ void cpa_wait0() {
    asm volatile("cp.async.wait_group 0;" ::: "memory");
}

// Async load of one x tile (64 rows x 130 cols, cols gl = t*TT-1 .. t*TT+128)
// into dst[c*132 + li]. Out-of-range columns are zero-filled (src-size 0).
__device__ __forceinline__ void load_tile_async(float* dst, const float* xb, int t)
{
    const int tid = threadIdx.x;
    const int l0 = t * TT - 1;
    unsigned base = (unsigned)__cvta_generic_to_shared(dst);
    for (int idx = tid; idx < 64 * 130; idx += 512) {
        int c = idx / 130;
        int li = idx - c * 130;
        int gl = l0 + li;
        int ok = (gl >= 0) && (gl < LSEQ);
        const float* src = xb + (long)c * LSEQ + (ok ? gl : 0);
        int sz = ok ? 4 : 0;
        unsigned d = base + (unsigned)((c * 132 + li) * 4);
        asm volatile("cp.async.ca.shared.global [%0], [%1], 4, %2;"
                     :: "r"(d), "l"(src), "r"(sz) : "memory");
    }
}

// ---------------------------------------------------------------------------
// K3: persistent, double-buffered: out = P @ dwconv3(Wv @ x).
// 512 threads, 1 CTA/SM, weights loaded once, cp.async pipelines x tiles.
// ---------------------------------------------------------------------------
__global__ __launch_bounds__(512, 1)
void k3_out(const float* __restrict__ x,
            const float* __restrict__ w_kv,
            const float* __restrict__ w_kv_dw,
            float* __restrict__ out)
{
    extern __shared__ float sm4[];
    float* xs0 = sm4;             // 8448
    float* xs1 = sm4 + 8448;      // 8448
    float* yv  = sm4 + 16896;     // 8448
    float* wsv = sm4 + 25344;     // 4352  [k][o]
    float* ps  = sm4 + 29696;     // 4352  [c][o]
    float* wdv = sm4 + 34048;     // 192
    // total 34240 floats = 136960 B

    const int tid = threadIdx.x;
    const int b = blockIdx.y;
    const float* xb = x + (long)b * 64 * LSEQ;

    // weights + P, once per CTA
    for (int idx = tid; idx < 4096; idx += 512) {
        int o = idx >> 6, k = idx & 63;
        wsv[k * 68 + o] = w_kv[(64 + o) * 64 + k];   // Wv rows 64..127
        ps[k * 68 + o]  = g_P[b * 4096 + idx];       // ps[c][o] = P[o][c]
    }
    for (int idx = tid; idx < 192; idx += 512)
        wdv[idx] = w_kv_dw[192 + idx];

    int t = blockIdx.x;
    if (t < NTILES) load_tile_async(xs0, xb, t);
    cpa_commit();
    cpa_wait0();
    __syncthreads();

    const int o0 = (tid >> 5) * 4;       // 16 o-blocks
    const int lB = (tid & 31) * 4;       // 32 l-blocks

    float* cur = xs0;
    float* nxt = xs1;

    for (; t < NTILES; t += G3X) {
        // prefetch next tile
        int tn = t + G3X;
        if (tn < NTILES) load_tile_async(nxt, xb, tn);
        cpa_commit();

        // GEMM1: yv = Wv @ x  (cols li 0..127)
        {
            u64 acc[4][2];
#pragma unroll
            for (int i = 0; i < 4; i++) { acc[i][0] = 0ull; acc[i][1] = 0ull; }
#pragma unroll 4
            for (int k = 0; k < 64; k++) {
                float4 av = *(const float4*)(wsv + k * 68 + o0);
                u64 a0 = dup2(av.x), a1 = dup2(av.y), a2 = dup2(av.z), a3 = dup2(av.w);
                ulonglong2 bv = *(const ulonglong2*)(cur + k * 132 + lB);
                fma2(acc[0][0], a0, bv.x); fma2(acc[0][1], a0, bv.y);
                fma2(acc[1][0], a1, bv.x); fma2(acc[1][1], a1, bv.y);
                fma2(acc[2][0], a2, bv.x); fma2(acc[2][1], a2, bv.y);
                fma2(acc[3][0], a3, bv.x); fma2(acc[3][1], a3, bv.y);
            }
#pragma unroll
            for (int i = 0; i < 4; i++) {
                *(u64*)(yv + (o0 + i) * 132 + lB)     = acc[i][0];
                *(u64*)(yv + (o0 + i) * 132 + lB + 2) = acc[i][1];
            }
        }
        __syncthreads();

        // dwconv: vs (= cur, overwritten) [c][l'], l' = 0..125
        for (int idx = tid; idx < 8192; idx += 512) {
            int c = idx >> 7, l = idx & 127;
            if (l < TT) {
                const float* yr = yv + c * 132 + l;
                cur[c * 132 + l] = wdv[c * 3] * yr[0] + wdv[c * 3 + 1] * yr[1]
                                 + wdv[c * 3 + 2] * yr[2];
            }
        }
        __syncthreads();

        // GEMM2: out = P @ v, direct store
        {
            u64 acc[4][2];
#pragma unroll
            for (int i = 0; i < 4; i++) { acc[i][0] = 0ull; acc[i][1] = 0ull; }
#pragma unroll 4
            for (int c = 0; c < 64; c++) {
                float4 av = *(const float4*)(ps + c * 68 + o0);
                u64 a0 = dup2(av.x), a1 = dup2(av.y), a2 = dup2(av.z), a3 = dup2(av.w);
                ulonglong2 bv = *(const ulonglong2*)(cur + c * 132 + lB);
                fma2(acc[0][0], a0, bv.x); fma2(acc[0][1], a0, bv.y);
                fma2(acc[1][0], a1, bv.x); fma2(acc[1][1], a1, bv.y);
                fma2(acc[2][0], a2, bv.x); fma2(acc[2][1], a2, bv.y);
                fma2(acc[3][0], a3, bv.x); fma2(acc[3][1], a3, bv.y);
            }
            const int gl = t * TT + lB;
            const bool ok0 = (gl < LSEQ);                   // lB <= 124 always
            const bool ok1 = (lB != 124) && (gl + 2 < LSEQ);
#pragma unroll
            for (int i = 0; i < 4; i++) {
                float* op = out + (long)(b * 64 + o0 + i) * LSEQ;
                if (ok0) *(float2*)(op + gl)     = unpack2(acc[i][0]);
                if (ok1) *(float2*)(op + gl + 2) = unpack2(acc[i][1]);
            }
        }

        cpa_wait0();
        __syncthreads();
        float* tmp = cur; cur = nxt; nxt = tmp;
    }
}

// ---------------------------------------------------------------------------
extern "C" void kernel_launch(void* const* d_in, const int* in_sizes, int n_in,
                              void* d_out, int out_size)
{
    const float* x           = (const float*)d_in[0];
    const float* w_kv        = (const float*)d_in[1];
    const float* w_kv_dw     = (const float*)d_in[2];
    const float* w_q         = (const float*)d_in[3];
    const float* w_q_dw      = (const float*)d_in[4];
    const float* w_proj      = (const float*)d_in[5];
    const float* temperature = (const float*)d_in[6];
    float* out = (float*)d_out;

    const int SM1  = 258 * 68 * 4;      // 70176
    const int SM2A = 3 * 4096 * 4;      // 49152
    const int SM2B = 9 * 4096 * 4;      // 147456
    const int SM3  = 34240 * 4;         // 136960
    cudaFuncSetAttribute(k1_gram, cudaFuncAttributeMaxDynamicSharedMemorySize, SM1);
    cudaFuncSetAttribute(k2a,     cudaFuncAttributeMaxDynamicSharedMemorySize, SM2A);
    cudaFuncSetAttribute(k2b,     cudaFuncAttributeMaxDynamicSharedMemorySize, SM2B);
    cudaFuncSetAttribute(k3_out,  cudaFuncAttributeMaxDynamicSharedMemorySize, SM3);

    k1_gram<<<dim3(G1X, NB), 256, SM1>>>(x);
    k2a<<<dim3(3, NB), 256, SM2A>>>(w_kv, w_q);
    k2b<<<NB, 256, SM2B>>>(x, w_kv, w_kv_dw, w_q, w_q_dw, w_proj, temperature);
    k3_out<<<dim3(G3X, NB), 512, SM3>>>(x, w_kv, w_kv_dw, out);
}

// round 10
// speedup vs baseline: 2.8207x; 1.5513x over previous
#include <cuda_runtime.h>
#include <math.h>

#define LSEQ 131072
#define NB 4
#define TT 126
#define NTILES ((LSEQ + TT - 1) / TT)   // 1041 (k3)
#define G3X 37              // k3 persistent grid.x
#define K1CTAS 37           // k1 persistent grid.x
#define T1 128              // k1 tile columns
#define NT1K (LSEQ / T1)    // 1024
#define P1 132              // k1 smem pitch (== 4 mod 32 -> conflict-free frags)

typedef unsigned long long u64;

// Scratch (no cudaMalloc allowed)
__device__ float g_part[NB * K1CTAS * 3 * 4096];  // partial G0,G1,G2 per CTA
__device__ float g_Z[NB * 5 * 4096];              // Z0,Z1,Z2,Z1t,Z2t
__device__ float g_gd[NB * 3 * 64];
__device__ float g_hd[NB * 3 * 64];
__device__ float g_P[NB * 4096];

// ---------------- packed f32x2 helpers (k3) ----------------
__device__ __forceinline__ u64 dup2(float f) {
    u64 r; asm("mov.b64 %0, {%1, %1};" : "=l"(r) : "f"(f)); return r;
}
__device__ __forceinline__ void fma2(u64& d, u64 a, u64 b) {
    asm("fma.rn.f32x2 %0, %1, %2, %0;" : "+l"(d) : "l"(a), "l"(b));
}
__device__ __forceinline__ float2 unpack2(u64 v) {
    float2 r; asm("mov.b64 {%0, %1}, %2;" : "=f"(r.x), "=f"(r.y) : "l"(v)); return r;
}

// ---------------- cp.async helpers ----------------
__device__ __forceinline__ unsigned s2u(const void* p) {
    unsigned a;
    asm("{ .reg .u64 t; cvta.to.shared.u64 t, %1; cvt.u32.u64 %0, t; }" : "=r"(a) : "l"(p));
    return a;
}
__device__ __forceinline__ void cpa16(unsigned d, const void* s) {
    asm volatile("cp.async.ca.shared.global [%0], [%1], 16;" :: "r"(d), "l"(s) : "memory");
}
__device__ __forceinline__ void cpa4(unsigned d, const void* s, int sz) {
    asm volatile("cp.async.ca.shared.global [%0], [%1], 4, %2;" :: "r"(d), "l"(s), "r"(sz) : "memory");
}
__device__ __forceinline__ void cpa_commit() {
    asm volatile("cp.async.commit_group;" ::: "memory");
}
__device__ __forceinline__ void cpa_wait0() {
    asm volatile("cp.async.wait_group 0;" ::: "memory");
}

// ---------------- tf32 mma.sync (sm_80+ path, NOT 'a'-gated) ----------------
__device__ __forceinline__ void mma8(float* c,
                                     unsigned a0, unsigned a1, unsigned a2, unsigned a3,
                                     unsigned b0, unsigned b1)
{
    asm volatile(
        "mma.sync.aligned.m16n8k8.row.col.f32.tf32.tf32.f32 "
        "{%0,%1,%2,%3}, {%4,%5,%6,%7}, {%8,%9}, {%0,%1,%2,%3};"
        : "+f"(c[0]), "+f"(c[1]), "+f"(c[2]), "+f"(c[3])
        : "r"(a0), "r"(a1), "r"(a2), "r"(a3), "r"(b0), "r"(b1));
}

// ---------------------------------------------------------------------------
// K1 fill: one x tile (64 rows x 130 cols, cols l0..l0+129) into dst[c*P1+li].
// Main 128 cols via 16B cp.async (always in-bounds); 2 halo cols predicated.
// ---------------------------------------------------------------------------
__device__ __forceinline__ void k1_fill(float* dst, const float* __restrict__ xb, int t)
{
    const int tid = threadIdx.x;
    const int l0 = t * T1;
    unsigned base = s2u(dst);
    for (int idx = tid; idx < 2048; idx += 256) {
        int c = idx >> 5, ch = idx & 31;
        const float* src = xb + (size_t)c * LSEQ + l0 + ch * 4;
        cpa16(base + (unsigned)((c * P1 + ch * 4) * 4), src);
    }
    for (int idx = tid; idx < 128; idx += 256) {
        int c = idx >> 1, li = T1 + (idx & 1);
        int gl = l0 + li;
        int ok = gl < LSEQ;
        const float* src = xb + (size_t)c * LSEQ + (ok ? gl : 0);
        cpa4(base + (unsigned)((c * P1 + li) * 4), src, ok ? 4 : 0);
    }
}

// ---------------------------------------------------------------------------
// K1: shifted Grams via tf32 mma.sync. G_s[c][d] = sum_m x_c(m) x_d(m+s).
// Grid (37, NB), 256 threads = 8 warps. Warp w: m-tile (w>>1)*16, n-half
// (w&1)*32; owns 4 n-tiles x 3 shifts = 12 m16n8 accum tiles for the whole
// strip. A-frag shared across all 12; B-frags for the 3 shifts share loads.
// ---------------------------------------------------------------------------
__global__ __launch_bounds__(256, 1)
void k1_mma(const float* __restrict__ x)
{
    extern __shared__ float sm1[];
    float* xs0 = sm1;              // 64*P1 = 8448
    float* xs1 = sm1 + 8448;       // 8448

    const int tid = threadIdx.x, lane = tid & 31, w = tid >> 5;
    const int b = blockIdx.y, jx = blockIdx.x;
    const float* xb = x + (size_t)b * 64 * LSEQ;

    const int m0 = (w >> 1) * 16;
    const int n0 = (w & 1) * 32;
    const int g = lane >> 2, jj = lane & 3;

    float acc[12][4];
#pragma unroll
    for (int i = 0; i < 12; i++)
#pragma unroll
        for (int q = 0; q < 4; q++) acc[i][q] = 0.f;

    int t = jx;
    k1_fill(xs0, xb, t);
    cpa_commit();
    cpa_wait0();
    __syncthreads();

    float* cur = xs0;
    float* nxt = xs1;

    for (; t < NT1K; t += K1CTAS) {
        int tn = t + K1CTAS;
        if (tn < NT1K) k1_fill(nxt, xb, tn);
        cpa_commit();

        const float* xc = cur;
#pragma unroll 2
        for (int kc = 0; kc < T1 / 8; kc++) {
            const int k0 = kc * 8;
            // A fragment: rows m0+g, m0+g+8; cols k0+jj, k0+jj+4
            const float* ar = xc + (m0 + g) * P1 + k0 + jj;
            unsigned a0 = __float_as_uint(ar[0]);
            unsigned a2 = __float_as_uint(ar[4]);
            unsigned a1 = __float_as_uint(ar[8 * P1]);
            unsigned a3 = __float_as_uint(ar[8 * P1 + 4]);
#pragma unroll
            for (int nt = 0; nt < 4; nt++) {
                // B fragments for shifts 0,1,2: row n0+nt*8+g, cols k0+jj+s, +4+s
                const float* br = xc + (n0 + nt * 8 + g) * P1 + k0 + jj;
                unsigned v0 = __float_as_uint(br[0]);
                unsigned v1 = __float_as_uint(br[1]);
                unsigned v2 = __float_as_uint(br[2]);
                unsigned u0 = __float_as_uint(br[4]);
                unsigned u1 = __float_as_uint(br[5]);
                unsigned u2 = __float_as_uint(br[6]);
                mma8(acc[nt * 3 + 0], a0, a1, a2, a3, v0, u0);
                mma8(acc[nt * 3 + 1], a0, a1, a2, a3, v1, u1);
                mma8(acc[nt * 3 + 2], a0, a1, a2, a3, v2, u2);
            }
        }

        cpa_wait0();
        __syncthreads();
        float* tmp = cur; cur = nxt; nxt = tmp;
    }

    // write partials: D[m][n] = G_s[m][n] fragments
    float* pb = g_part + ((size_t)(b * K1CTAS + jx) * 3) * 4096;
#pragma unroll
    for (int nt = 0; nt < 4; nt++)
#pragma unroll
        for (int s = 0; s < 3; s++) {
            const float* a = acc[nt * 3 + s];
            int col = n0 + nt * 8 + 2 * jj;
            int r0 = m0 + g;
            pb[s * 4096 + r0 * 64 + col]           = a[0];
            pb[s * 4096 + r0 * 64 + col + 1]       = a[1];
            pb[s * 4096 + (r0 + 8) * 64 + col]     = a[2];
            pb[s * 4096 + (r0 + 8) * 64 + col + 1] = a[3];
        }
}

// ---------------------------------------------------------------------------
// 64x64x64 matmul: C = A @ B (row-major smem); At=true -> C = A^T @ B
// ---------------------------------------------------------------------------
__device__ __forceinline__ void mm64(const float* __restrict__ A,
                                     const float* __restrict__ B,
                                     float* __restrict__ C, int tid, bool At)
{
    const int i0 = (tid >> 4) * 4, j0 = (tid & 15) * 4;
    float acc[4][4] = {};
    for (int k = 0; k < 64; k++) {
        float a[4];
#pragma unroll
        for (int i = 0; i < 4; i++) a[i] = At ? A[k * 64 + i0 + i] : A[(i0 + i) * 64 + k];
        float4 bv = *(const float4*)(B + k * 64 + j0);
        float bb[4] = {bv.x, bv.y, bv.z, bv.w};
#pragma unroll
        for (int i = 0; i < 4; i++)
#pragma unroll
            for (int j = 0; j < 4; j++) acc[i][j] = fmaf(a[i], bb[j], acc[i][j]);
    }
#pragma unroll
    for (int i = 0; i < 4; i++)
#pragma unroll
        for (int j = 0; j < 4; j++) C[(i0 + i) * 64 + j0 + j] = acc[i][j];
}

// ---------------------------------------------------------------------------
// K2a: reduce G_s; gd_s = diag(Wq G_s Wq^T); Z_s = G_s Wk^T (store); hd_s;
// if s>0 also Zt_s = G_s^T Wk^T.
// ---------------------------------------------------------------------------
__global__ __launch_bounds__(256)
void k2a(const float* __restrict__ w_kv, const float* __restrict__ w_q)
{
    extern __shared__ float sm2[];
    float* sG  = sm2;
    float* sWT = sm2 + 4096;
    float* sM  = sm2 + 8192;
    const int tid = threadIdx.x;
    const int s = blockIdx.x, b = blockIdx.y;

    for (int idx = tid; idx < 4096; idx += 256) {
        const float* p = g_part + ((size_t)(b * K1CTAS) * 3 + s) * 4096 + idx;
        float acc = 0.f;
        for (int blk = 0; blk < K1CTAS; blk++) acc += p[(size_t)blk * 3 * 4096];
        sG[idx] = acc;
    }
    for (int idx = tid; idx < 4096; idx += 256)
        sWT[(idx & 63) * 64 + (idx >> 6)] = w_q[idx];
    __syncthreads();

    mm64(sG, sWT, sM, tid, false);          // E = G_s @ Wq^T
    __syncthreads();
    if (tid < 64) {
        float acc = 0.f;
        for (int k = 0; k < 64; k++) acc = fmaf(sWT[k * 64 + tid], sM[k * 64 + tid], acc);
        g_gd[(b * 3 + s) * 64 + tid] = acc;
    }
    __syncthreads();

    for (int idx = tid; idx < 4096; idx += 256)
        sWT[(idx & 63) * 64 + (idx >> 6)] = w_kv[idx];   // Wk rows 0..63
    __syncthreads();

    mm64(sG, sWT, sM, tid, false);          // Z = G_s @ Wk^T
    __syncthreads();
    float* gZ = g_Z + (b * 5 + s) * 4096;
    for (int idx = tid; idx < 4096; idx += 256) gZ[idx] = sM[idx];
    if (tid < 64) {
        float acc = 0.f;
        for (int k = 0; k < 64; k++) acc = fmaf(sWT[k * 64 + tid], sM[k * 64 + tid], acc);
        g_hd[(b * 3 + s) * 64 + tid] = acc;
    }
    __syncthreads();

    if (s > 0) {
        mm64(sG, sWT, sM, tid, true);       // Zt = G_s^T @ Wk^T
        __syncthreads();
        float* gZt = g_Z + (b * 5 + 2 + s) * 4096;
        for (int idx = tid; idx < 4096; idx += 256) gZt[idx] = sM[idx];
    }
}

// ---------------------------------------------------------------------------
// K2b: assemble S (+ edge corrections), norms, softmax, P = Wproj @ attn.
// ---------------------------------------------------------------------------
__global__ __launch_bounds__(256)
void k2b(const float* __restrict__ x,
         const float* __restrict__ w_kv,
         const float* __restrict__ w_kv_dw,
         const float* __restrict__ w_q,
         const float* __restrict__ w_q_dw,
         const float* __restrict__ w_proj,
         const float* __restrict__ temperature)
{
    extern __shared__ float sm3[];
    float* sZ0  = sm3;
    float* sZ1  = sm3 + 4096;
    float* sZ2  = sm3 + 8192;
    float* sZ1t = sm3 + 12288;
    float* sZ2t = sm3 + 16384;
    float* sW   = sm3 + 20480;
    float* sR   = sm3 + 24576;
    float* sS   = sm3 + 28672;
    float* sP   = sm3 + 32768;

    __shared__ float x0s[64], xLs[64], u0s[64], uLs[64], v0s[64], vLs[64];
    __shared__ float aqs[3][64], bks[3][64], nqs[64], nks[64];

    const int tid = threadIdx.x;
    const int b = blockIdx.x;
    const float tempv = temperature[b];

    for (int idx = tid; idx < 5 * 4096; idx += 256) sm3[idx] = g_Z[b * 5 * 4096 + idx];
    for (int idx = tid; idx < 4096; idx += 256) sW[idx] = w_q[idx];
    if (tid < 64) {
        const int c = tid;
        x0s[c] = x[(b * 64 + c) * LSEQ];
        xLs[c] = x[(b * 64 + c) * LSEQ + LSEQ - 1];
#pragma unroll
        for (int e = 0; e < 3; e++) {
            aqs[e][c] = w_q_dw[c * 3 + e];
            bks[e][c] = w_kv_dw[c * 3 + e];
        }
    }
    __syncthreads();

    if (tid < 64) {
        const int c = tid;
        float a0 = 0.f, aL = 0.f, q0 = 0.f, qL = 0.f;
        for (int k = 0; k < 64; k++) {
            float wk = w_kv[c * 64 + k], wq = w_q[c * 64 + k];
            a0 = fmaf(wk, x0s[k], a0);  aL = fmaf(wk, xLs[k], aL);
            q0 = fmaf(wq, x0s[k], q0);  qL = fmaf(wq, xLs[k], qL);
        }
        u0s[c] = a0; uLs[c] = aL; v0s[c] = q0; vLs[c] = qL;
    }
    __syncthreads();

    for (int dd = 0; dd < 3; dd++) {
        for (int idx = tid; idx < 4096; idx += 256) {
            const int i = idx >> 6, j = idx & 63;
            float r;
            if (dd == 0) {
                r = (sZ0[idx] - xLs[i] * uLs[j]) * bks[0][j]
                  + sZ1[idx] * bks[1][j] + sZ2[idx] * bks[2][j];
            } else if (dd == 1) {
                r = sZ1t[idx] * bks[0][j] + sZ0[idx] * bks[1][j] + sZ1[idx] * bks[2][j];
            } else {
                r = sZ2t[idx] * bks[0][j] + sZ1t[idx] * bks[1][j]
                  + (sZ0[idx] - x0s[i] * u0s[j]) * bks[2][j];
            }
            sR[idx] = r;
        }
        __syncthreads();
        {
            const int i0 = (tid >> 4) * 4, j0 = (tid & 15) * 4;
            float acc[4][4] = {};
            for (int k = 0; k < 64; k++) {
                float a[4];
#pragma unroll
                for (int i = 0; i < 4; i++) a[i] = sW[(i0 + i) * 64 + k];
                float4 bv = *(const float4*)(sR + k * 64 + j0);
                float bb[4] = {bv.x, bv.y, bv.z, bv.w};
#pragma unroll
                for (int i = 0; i < 4; i++)
#pragma unroll
                    for (int j = 0; j < 4; j++) acc[i][j] = fmaf(a[i], bb[j], acc[i][j]);
            }
#pragma unroll
            for (int i = 0; i < 4; i++) {
                float scale = aqs[dd][i0 + i];
#pragma unroll
                for (int j = 0; j < 4; j++) {
                    if (dd == 0) sS[(i0 + i) * 64 + j0 + j] = scale * acc[i][j];
                    else         sS[(i0 + i) * 64 + j0 + j] += scale * acc[i][j];
                }
            }
        }
        __syncthreads();
    }

    if (tid < 64) {
        const int c = tid;
        float g0 = g_gd[(b * 3 + 0) * 64 + c], g1 = g_gd[(b * 3 + 1) * 64 + c],
              g2 = g_gd[(b * 3 + 2) * 64 + c];
        float h0 = g_hd[(b * 3 + 0) * 64 + c], h1 = g_hd[(b * 3 + 1) * 64 + c],
              h2 = g_hd[(b * 3 + 2) * 64 + c];
        float am = aqs[0][c], a0 = aqs[1][c], ap = aqs[2][c];
        float bm = bks[0][c], b0 = bks[1][c], bp = bks[2][c];
        float qq = am * am * (g0 - vLs[c] * vLs[c]) + a0 * a0 * g0
                 + ap * ap * (g0 - v0s[c] * v0s[c])
                 + 2.f * (am * a0 + a0 * ap) * g1 + 2.f * am * ap * g2;
        float kk = bm * bm * (h0 - uLs[c] * uLs[c]) + b0 * b0 * h0
                 + bp * bp * (h0 - u0s[c] * u0s[c])
                 + 2.f * (bm * b0 + b0 * bp) * h1 + 2.f * bm * bp * h2;
        nqs[c] = fmaxf(sqrtf(qq), 1e-12f);
        nks[c] = fmaxf(sqrtf(kk), 1e-12f);
    }
    __syncthreads();

    for (int idx = tid; idx < 4096; idx += 256) {
        const int i = idx >> 6, j = idx & 63;
        sS[idx] = tempv * sS[idx] / (nqs[i] * nks[j]);
    }
    __syncthreads();

    if (tid < 64) {
        const int c = tid;
        float m = -1e30f;
        for (int j = 0; j < 64; j++) m = fmaxf(m, sS[c * 64 + j]);
        float sum = 0.f;
        for (int j = 0; j < 64; j++) {
            float e = expf(sS[c * 64 + j] - m);
            sS[c * 64 + j] = e; sum += e;
        }
        float inv = 1.f / sum;
        for (int j = 0; j < 64; j++) sS[c * 64 + j] *= inv;
    }
    __syncthreads();
    for (int idx = tid; idx < 4096; idx += 256) sW[idx] = w_proj[idx];
    __syncthreads();

    mm64(sW, sS, sP, tid, false);
    __syncthreads();
    for (int idx = tid; idx < 4096; idx += 256) g_P[b * 4096 + idx] = sP[idx];
}

// ---------------------------------------------------------------------------
// K3: persistent, double-buffered f32x2 (unchanged, round-7 passing version).
// ---------------------------------------------------------------------------
__device__ __forceinline__ void load_tile_async(float* dst, const float* xb, int t)
{
    const int tid = threadIdx.x;
    const int l0 = t * TT - 1;
    unsigned base = s2u(dst);
    for (int idx = tid; idx < 64 * 130; idx += 512) {
        int c = idx / 130;
        int li = idx - c * 130;
        int gl = l0 + li;
        int ok = (gl >= 0) && (gl < LSEQ);
        const float* src = xb + (size_t)c * LSEQ + (ok ? gl : 0);
        cpa4(base + (unsigned)((c * 132 + li) * 4), src, ok ? 4 : 0);
    }
}

__global__ __launch_bounds__(512, 1)
void k3_out(const float* __restrict__ x,
            const float* __restrict__ w_kv,
            const float* __restrict__ w_kv_dw,
            float* __restrict__ out)
{
    extern __shared__ float sm4[];
    float* xs0 = sm4;
    float* xs1 = sm4 + 8448;
    float* yv  = sm4 + 16896;
    float* wsv = sm4 + 25344;
    float* ps  = sm4 + 29696;
    float* wdv = sm4 + 34048;

    const int tid = threadIdx.x;
    const int b = blockIdx.y;
    const float* xb = x + (size_t)b * 64 * LSEQ;

    for (int idx = tid; idx < 4096; idx += 512) {
        int o = idx >> 6, k = idx & 63;
        wsv[k * 68 + o] = w_kv[(64 + o) * 64 + k];
        ps[k * 68 + o]  = g_P[b * 4096 + idx];
    }
    for (int idx = tid; idx < 192; idx += 512)
        wdv[idx] = w_kv_dw[192 + idx];

    int t = blockIdx.x;
    if (t < NTILES) load_tile_async(xs0, xb, t);
    cpa_commit();
    cpa_wait0();
    __syncthreads();

    const int o0 = (tid >> 5) * 4;
    const int lB = (tid & 31) * 4;

    float* cur = xs0;
    float* nxt = xs1;

    for (; t < NTILES; t += G3X) {
        int tn = t + G3X;
        if (tn < NTILES) load_tile_async(nxt, xb, tn);
        cpa_commit();

        {
            u64 acc[4][2];
#pragma unroll
            for (int i = 0; i < 4; i++) { acc[i][0] = 0ull; acc[i][1] = 0ull; }
#pragma unroll 4
            for (int k = 0; k < 64; k++) {
                float4 av = *(const float4*)(wsv + k * 68 + o0);
                u64 a0 = dup2(av.x), a1 = dup2(av.y), a2 = dup2(av.z), a3 = dup2(av.w);
                ulonglong2 bv = *(const ulonglong2*)(cur + k * 132 + lB);
                fma2(acc[0][0], a0, bv.x); fma2(acc[0][1], a0, bv.y);
                fma2(acc[1][0], a1, bv.x); fma2(acc[1][1], a1, bv.y);
                fma2(acc[2][0], a2, bv.x); fma2(acc[2][1], a2, bv.y);
                fma2(acc[3][0], a3, bv.x); fma2(acc[3][1], a3, bv.y);
            }
#pragma unroll
            for (int i = 0; i < 4; i++) {
                *(u64*)(yv + (o0 + i) * 132 + lB)     = acc[i][0];
                *(u64*)(yv + (o0 + i) * 132 + lB + 2) = acc[i][1];
            }
        }
        __syncthreads();

        for (int idx = tid; idx < 8192; idx += 512) {
            int c = idx >> 7, l = idx & 127;
            if (l < TT) {
                const float* yr = yv + c * 132 + l;
                cur[c * 132 + l] = wdv[c * 3] * yr[0] + wdv[c * 3 + 1] * yr[1]
                                 + wdv[c * 3 + 2] * yr[2];
            }
        }
        __syncthreads();

        {
            u64 acc[4][2];
#pragma unroll
            for (int i = 0; i < 4; i++) { acc[i][0] = 0ull; acc[i][1] = 0ull; }
#pragma unroll 4
            for (int c = 0; c < 64; c++) {
                float4 av = *(const float4*)(ps + c * 68 + o0);
                u64 a0 = dup2(av.x), a1 = dup2(av.y), a2 = dup2(av.z), a3 = dup2(av.w);
                ulonglong2 bv = *(const ulonglong2*)(cur + c * 132 + lB);
                fma2(acc[0][0], a0, bv.x); fma2(acc[0][1], a0, bv.y);
                fma2(acc[1][0], a1, bv.x); fma2(acc[1][1], a1, bv.y);
                fma2(acc[2][0], a2, bv.x); fma2(acc[2][1], a2, bv.y);
                fma2(acc[3][0], a3, bv.x); fma2(acc[3][1], a3, bv.y);
            }
            const int gl = t * TT + lB;
            const bool ok0 = (gl < LSEQ);
            const bool ok1 = (lB != 124) && (gl + 2 < LSEQ);
#pragma unroll
            for (int i = 0; i < 4; i++) {
                float* op = out + (size_t)(b * 64 + o0 + i) * LSEQ;
                if (ok0) *(float2*)(op + gl)     = unpack2(acc[i][0]);
                if (ok1) *(float2*)(op + gl + 2) = unpack2(acc[i][1]);
            }
        }

        cpa_wait0();
        __syncthreads();
        float* tmp = cur; cur = nxt; nxt = tmp;
    }
}

// ---------------------------------------------------------------------------
extern "C" void kernel_launch(void* const* d_in, const int* in_sizes, int n_in,
                              void* d_out, int out_size)
{
    const float* x           = (const float*)d_in[0];
    const float* w_kv        = (const float*)d_in[1];
    const float* w_kv_dw     = (const float*)d_in[2];
    const float* w_q         = (const float*)d_in[3];
    const float* w_q_dw      = (const float*)d_in[4];
    const float* w_proj      = (const float*)d_in[5];
    const float* temperature = (const float*)d_in[6];
    float* out = (float*)d_out;

    const int SM1  = 2 * 8448 * 4;      // 67584
    const int SM2A = 3 * 4096 * 4;
    const int SM2B = 9 * 4096 * 4;
    const int SM3  = 34240 * 4;
    cudaFuncSetAttribute(k1_mma, cudaFuncAttributeMaxDynamicSharedMemorySize, SM1);
    cudaFuncSetAttribute(k2a,    cudaFuncAttributeMaxDynamicSharedMemorySize, SM2A);
    cudaFuncSetAttribute(k2b,    cudaFuncAttributeMaxDynamicSharedMemorySize, SM2B);
    cudaFuncSetAttribute(k3_out, cudaFuncAttributeMaxDynamicSharedMemorySize, SM3);

    k1_mma<<<dim3(K1CTAS, NB), 256, SM1>>>(x);
    k2a<<<dim3(3, NB), 256, SM2A>>>(w_kv, w_q);
    k2b<<<NB, 256, SM2B>>>(x, w_kv, w_kv_dw, w_q, w_q_dw, w_proj, temperature);
    k3_out<<<dim3(G3X, NB), 512, SM3>>>(x, w_kv, w_kv_dw, out);
}